// round 9
// baseline (speedup 1.0000x reference)
#include <cuda_runtime.h>
#include <cuda_fp16.h>
#include <mma.h>
#include <cstdint>

using namespace nvcuda;

namespace {
constexpr int NKEY = 49;
constexpr int QN_  = 196;
constexpr int DIM_ = 384;
constexpr int NH_  = 12;
constexpr int HD_  = 32;
constexpr int CQ_  = 192;
constexpr float SCALE_ = 0.17677669529663687f;

constexpr int NT    = 384;   // 12 warps
constexpr int NW    = 12;
constexpr int CHUNK = 80;    // q rows per chunk -> 3 weight passes (80+80+36)
constexpr int MTMAX = 5;
constexpr int NKP   = 64;    // padded keys / kv rows

constexpr int SKVH = 392;    // K/V row stride (halves), 784B -> 16B phase shift
constexpr int SQP  = 392;    // qp / x row stride (halves)
constexpr int SQIN = 200;    // q-input row stride (halves)
constexpr int STGF = 68;     // attention staging stride (f32)

// smem byte offsets (stg/qin/ost overlay; s_x overlays s_qp)
constexpr int OFF_K   = 0;                         // 64*392*2 = 50176
constexpr int OFF_V   = 50176;
constexpr int OFF_QP  = 100352;                    // 80*392*2 = 62720 (s_x overlays)
constexpr int OFF_SCR = 163072;                    // max(qin 32000, stg 52224, ost 36864)
constexpr int OFF_QC  = OFF_SCR + 52224;           // 215296: 196 ints
constexpr int OFF_ONE = OFF_QC + 784;              // 216080
constexpr int SMEM_BYTES = OFF_ONE + 512;          // 216592

using FragA  = wmma::fragment<wmma::matrix_a, 16, 16, 16, __half, wmma::row_major>;
using FragBR = wmma::fragment<wmma::matrix_b, 16, 16, 16, __half, wmma::row_major>;
using FragBC = wmma::fragment<wmma::matrix_b, 16, 16, 16, __half, wmma::col_major>;
using FragC  = wmma::fragment<wmma::accumulator, 16, 16, 16, float>;
using FragCH = wmma::fragment<wmma::accumulator, 16, 16, 16, __half>;

constexpr int NF_KV = 25 * 48;   // 24 k-steps + bias, 48 n-tiles
constexpr int NF_Q  = 13 * 24;   // 12 + bias, 24 n-tiles
constexpr int NF_P  = 25 * 12;   // 24 + bias, 12 n-tiles
}

__device__ uint4 g_wkv_f[NF_KV * 32];
__device__ uint4 g_wq_f [NF_Q  * 32];
__device__ uint4 g_wp_f [NF_P  * 32];
__device__ float g_bias_f[NH_ * 49 * NKEY];

__device__ __forceinline__ void expand_b(FragBR& f, uint4 v) {
    unsigned int w[4] = {v.x, v.y, v.z, v.w};
#pragma unroll
    for (int i = 0; i < 4; ++i) {
        const __half2 h2 = *reinterpret_cast<const __half2*>(&w[i]);
        f.x[2 * i]     = __low2half(h2);
        f.x[2 * i + 1] = __high2half(h2);
    }
}

__device__ __forceinline__ void cvt_store_half(__half* dst, int ld, const FragC& c) {
    FragCH h;
#pragma unroll
    for (int i = 0; i < 8; ++i) h.x[i] = __float2half_rn(c.x[i]);
    wmma::store_matrix_sync(dst, h, ld, wmma::mem_row_major);
}

// ---------------- setup kernels ----------------
__global__ void pack_frags(const float* __restrict__ w_kv, const float* __restrict__ b_kv,
                           const float* __restrict__ w_q,  const float* __restrict__ b_q,
                           const float* __restrict__ w_proj, const float* __restrict__ b_proj) {
    __shared__ __half tiles[8][256];
    const int w    = blockIdx.x * 8 + (threadIdx.x >> 5);
    const int lane = threadIdx.x & 31;
    __half* tile = tiles[threadIdx.x >> 5];
    uint4* dst;
    if (w < NF_KV) {
        const int ks = w / 48, nt = w - ks * 48, n0 = nt * 16;
        for (int e = lane; e < 256; e += 32) {
            const int r = e >> 4, c = e & 15;
            float v;
            if (ks < 24) v = w_kv[(ks * 16 + r) * 768 + n0 + c];
            else         v = (r == 0) ? b_kv[n0 + c] : 0.0f;
            tile[e] = __float2half_rn(v);
        }
        dst = g_wkv_f + w * 32;
    } else if (w < NF_KV + NF_Q) {
        const int w2 = w - NF_KV, ks = w2 / 24, nt = w2 - ks * 24, n0 = nt * 16;
        for (int e = lane; e < 256; e += 32) {
            const int r = e >> 4, c = e & 15;
            float v;
            if (ks < 12) v = w_q[(ks * 16 + r) * DIM_ + n0 + c] * SCALE_;
            else         v = (r == 0) ? b_q[n0 + c] * SCALE_ : 0.0f;
            tile[e] = __float2half_rn(v);
        }
        dst = g_wq_f + w2 * 32;
    } else if (w < NF_KV + NF_Q + NF_P) {
        const int w3 = w - NF_KV - NF_Q, ks = w3 / 12, nt = w3 - ks * 12, n0 = nt * 16;
        for (int e = lane; e < 256; e += 32) {
            const int r = e >> 4, c = e & 15;
            float v;
            if (ks < 24) v = w_proj[(ks * 16 + r) * CQ_ + n0 + c];
            else         v = (r == 0) ? b_proj[n0 + c] : 0.0f;
            tile[e] = __float2half_rn(v);
        }
        dst = g_wp_f + w3 * 32;
    } else return;
    __syncwarp();
    FragBR f;
    wmma::load_matrix_sync(f, tile, 16);
    unsigned int w4[4];
#pragma unroll
    for (int i = 0; i < 4; ++i) {
        __half2 h2 = __halves2half2(f.x[2 * i], f.x[2 * i + 1]);
        w4[i] = *reinterpret_cast<unsigned int*>(&h2);
    }
    dst[lane] = make_uint4(w4[0], w4[1], w4[2], w4[3]);
}

__global__ void pack_bias(const float* __restrict__ bias_table) {
    const int idx = blockIdx.x * blockDim.x + threadIdx.x;
    if (idx >= NH_ * 49 * NKEY) return;
    const int h   = idx / (49 * NKEY);
    const int rem = idx - h * 49 * NKEY;
    const int qc  = rem / NKEY;
    const int key = rem - qc * NKEY;
    const int qi2 = qc / 7, qj2 = qc - qi2 * 7;
    const int kp  = key * 4;
    const int ki  = kp / 14, kj = kp - ki * 14;
    const int dh  = qi2 - (ki >> 1) + 6;
    const int dw  = qj2 - (kj >> 1) + 6;
    g_bias_f[idx] = bias_table[(dh * 13 + dw) * NH_ + h];
}

// ---------------- main kernel ----------------
__global__ __launch_bounds__(NT, 1)
void wca_kernel(const float* __restrict__ kv, const float* __restrict__ q,
                float* __restrict__ out)
{
    extern __shared__ char smb[];
    __half* s_k   = (__half*)(smb + OFF_K);
    __half* s_v   = (__half*)(smb + OFF_V);
    __half* s_qp  = (__half*)(smb + OFF_QP);    // 80x392 half (phase1: s_x 64x392)
    __half* s_x   = (__half*)(smb + OFF_QP);
    __half* s_qin = (__half*)(smb + OFF_SCR);   // 80x200 half (phase 2a-2b)
    float*  s_stg = (float*)(smb + OFF_SCR);    // 12 x (16x68) f32 (phase 2c)
    float*  s_ost = (float*)(smb + OFF_SCR);    // 48x192 f32 (partial-chunk 2d)
    int*    s_qc  = (int*)(smb + OFF_QC);       // 196 bias-cell ids
    __half* s_one = (__half*)(smb + OFF_ONE);   // 16x16 ones-column tile

    const int b    = blockIdx.x;
    const int tid  = threadIdx.x;
    const int wid  = tid >> 5;
    const int lane = tid & 31;
    float* wstg = s_stg + wid * (16 * STGF);

    // ---- phase 0: X load (49 rows) + zero pad rows, ones tile, bias cells ----
    {
        const float4* src = (const float4*)(kv + (size_t)b * NKEY * DIM_);
        for (int i = tid; i < NKEY * 96; i += NT) {
            const int r = i / 96, c4 = (i - r * 96) * 4;
            const float4 v = src[i];
            __half* d = s_x + r * SQP + c4;
            d[0] = __float2half_rn(v.x); d[1] = __float2half_rn(v.y);
            d[2] = __float2half_rn(v.z); d[3] = __float2half_rn(v.w);
        }
        for (int i = tid; i < (NKP - NKEY) * SQP; i += NT)
            s_x[NKEY * SQP + i] = __float2half_rn(0.0f);
        if (tid < 256) s_one[tid] = __float2half_rn((tid & 15) == 0 ? 1.0f : 0.0f);
        if (tid < QN_) {
            const int qi = tid / 14, qj = tid - qi * 14;
            s_qc[tid] = (qi >> 1) * 7 + (qj >> 1);
        }
    }
    __syncthreads();

    // ---- phase 1: kv projection, B-stationary over all 4 m-tiles ----
    {
        FragA ones;
        wmma::load_matrix_sync(ones, s_one, 16);
        for (int j = 0; j < 2; ++j) {
            const int nt0 = (wid * 2 + j) * 2;       // 2 n-tiles per job
            FragC c[4][2];
#pragma unroll
            for (int m = 0; m < 4; ++m) {
                wmma::fill_fragment(c[m][0], 0.0f);
                wmma::fill_fragment(c[m][1], 0.0f);
            }
            uint4 nb0 = g_wkv_f[nt0 * 32 + lane];
            uint4 nb1 = g_wkv_f[(nt0 + 1) * 32 + lane];
            for (int ks = 0; ks < 24; ++ks) {
                FragBR b0, b1;
                expand_b(b0, nb0);
                expand_b(b1, nb1);
                nb0 = g_wkv_f[((ks + 1) * 48 + nt0) * 32 + lane];
                nb1 = g_wkv_f[((ks + 1) * 48 + nt0 + 1) * 32 + lane];
#pragma unroll
                for (int m = 0; m < 4; ++m) {
                    FragA a;
                    wmma::load_matrix_sync(a, s_x + m * 16 * SQP + ks * 16, SQP);
                    wmma::mma_sync(c[m][0], a, b0, c[m][0]);
                    wmma::mma_sync(c[m][1], a, b1, c[m][1]);
                }
            }
            {   // bias k-step
                FragBR b0, b1;
                expand_b(b0, nb0);
                expand_b(b1, nb1);
#pragma unroll
                for (int m = 0; m < 4; ++m) {
                    wmma::mma_sync(c[m][0], ones, b0, c[m][0]);
                    wmma::mma_sync(c[m][1], ones, b1, c[m][1]);
                }
            }
#pragma unroll
            for (int t = 0; t < 2; ++t) {
                const int colg = (nt0 + t) * 16;
                __half* dst = (colg < DIM_) ? (s_k + colg) : (s_v + colg - DIM_);
#pragma unroll
                for (int m = 0; m < 4; ++m)
                    cvt_store_half(dst + m * 16 * SKVH, SKVH, c[m][t]);
            }
        }
    }
    __syncthreads();

    // ---- phase 2: q chunks of up to 80 rows ----
    for (int q0 = 0; q0 < QN_; q0 += CHUNK) {
        const int nr = min(CHUNK, QN_ - q0);
        const int mt = (nr + 15) >> 4;               // 5,5,3

        // 2a: q chunk -> half (zero pad to mt*16 rows)
        {
            const float4* src = (const float4*)(q + (size_t)b * QN_ * CQ_ + (size_t)q0 * CQ_);
            for (int i = tid; i < mt * 16 * 48; i += NT) {
                const int r = i / 48, c4 = (i - r * 48) * 4;
                float4 v = make_float4(0.f, 0.f, 0.f, 0.f);
                if (r < nr) v = src[i];
                __half* d = s_qin + r * SQIN + c4;
                d[0] = __float2half_rn(v.x); d[1] = __float2half_rn(v.y);
                d[2] = __float2half_rn(v.z); d[3] = __float2half_rn(v.w);
            }
        }
        __syncthreads();

        // 2b: q projection — warp = 2 n-tiles x mt m-tiles
        {
            FragA ones;
            wmma::load_matrix_sync(ones, s_one, 16);
            const int nt0 = wid * 2;
            FragC c[MTMAX][2];
            for (int m = 0; m < mt; ++m) {
                wmma::fill_fragment(c[m][0], 0.0f);
                wmma::fill_fragment(c[m][1], 0.0f);
            }
            uint4 nb0 = g_wq_f[nt0 * 32 + lane];
            uint4 nb1 = g_wq_f[(nt0 + 1) * 32 + lane];
            for (int ks = 0; ks < 12; ++ks) {
                FragBR b0, b1;
                expand_b(b0, nb0);
                expand_b(b1, nb1);
                nb0 = g_wq_f[((ks + 1) * 24 + nt0) * 32 + lane];
                nb1 = g_wq_f[((ks + 1) * 24 + nt0 + 1) * 32 + lane];
                for (int m = 0; m < mt; ++m) {
                    FragA a;
                    wmma::load_matrix_sync(a, s_qin + m * 16 * SQIN + ks * 16, SQIN);
                    wmma::mma_sync(c[m][0], a, b0, c[m][0]);
                    wmma::mma_sync(c[m][1], a, b1, c[m][1]);
                }
            }
            {
                FragBR b0, b1;
                expand_b(b0, nb0);
                expand_b(b1, nb1);
                for (int m = 0; m < mt; ++m) {
                    wmma::mma_sync(c[m][0], ones, b0, c[m][0]);
                    wmma::mma_sync(c[m][1], ones, b1, c[m][1]);
                }
            }
            for (int m = 0; m < mt; ++m) {
                cvt_store_half(s_qp + m * 16 * SQP + nt0 * 16, SQP, c[m][0]);
                cvt_store_half(s_qp + m * 16 * SQP + (nt0 + 1) * 16, SQP, c[m][1]);
            }
        }
        __syncthreads();

        // 2c: attention — warp = head; mt sub-chunks of 16 rows
        {
            const int h = wid;
            const int base = h * HD_;
            for (int s = 0; s < mt; ++s) {
                const int r0 = s * 16;
                FragC sf[4];
#pragma unroll
                for (int t = 0; t < 4; ++t) wmma::fill_fragment(sf[t], 0.0f);
#pragma unroll
                for (int ks = 0; ks < 2; ++ks) {
                    FragA a;
                    wmma::load_matrix_sync(a, s_qp + r0 * SQP + base + ks * 16, SQP);
#pragma unroll
                    for (int t = 0; t < 4; ++t) {
                        FragBC bk;
                        wmma::load_matrix_sync(bk, s_k + (t * 16) * SKVH + base + ks * 16, SKVH);
                        wmma::mma_sync(sf[t], a, bk, sf[t]);
                    }
                }
#pragma unroll
                for (int t = 0; t < 4; ++t)
                    wmma::store_matrix_sync(wstg + t * 16, sf[t], STGF, wmma::mem_row_major);
                __syncwarp();

                // softmax: 2 lanes per row; pre-normalized half P over 64 keys
                {
                    const int r = lane >> 1, par = lane & 1;
                    float* row = wstg + r * STGF;
                    const float* brow = g_bias_f + (h * 49 + s_qc[min(q0 + r0 + r, QN_ - 1)]) * NKEY;
                    float vals[25];
                    int cnt = 0;
                    float mx = -1e30f;
                    for (int c = par; c < NKEY; c += 2) {
                        const float v = row[c] + brow[c];
                        vals[cnt++] = v;
                        mx = fmaxf(mx, v);
                    }
                    mx = fmaxf(mx, __shfl_xor_sync(0xffffffffu, mx, 1));
                    float ssum = 0.f;
                    for (int i = 0; i < cnt; ++i) {
                        const float p = __expf(vals[i] - mx);
                        vals[i] = p;
                        ssum += p;
                    }
                    ssum += __shfl_xor_sync(0xffffffffu, ssum, 1);
                    const float inv = 1.0f / ssum;
                    __half* prow = (__half*)wstg + r * (STGF * 2);
                    int i = 0;
                    for (int c = par; c < 64; c += 2) {
                        const float p = (c < NKEY) ? vals[i++] * inv : 0.0f;
                        prow[c] = __float2half_rn(p);
                    }
                }
                __syncwarp();

                // O = Pn V over 64 keys
                FragC o[2];
                wmma::fill_fragment(o[0], 0.0f);
                wmma::fill_fragment(o[1], 0.0f);
#pragma unroll
                for (int ks = 0; ks < 4; ++ks) {
                    FragA a;
                    wmma::load_matrix_sync(a, (__half*)wstg + ks * 16, STGF * 2);
#pragma unroll
                    for (int t = 0; t < 2; ++t) {
                        FragBR bv;
                        wmma::load_matrix_sync(bv, s_v + ks * 16 * SKVH + base + t * 16, SKVH);
                        wmma::mma_sync(o[t], a, bv, o[t]);
                    }
                }
#pragma unroll
                for (int t = 0; t < 2; ++t)
                    cvt_store_half(s_qp + r0 * SQP + base + t * 16, SQP, o[t]);
                __syncwarp();
            }
        }
        __syncthreads();

        // 2d: out projection — warp = 1 n-tile x mt m-tiles
        {
            FragA ones;
            wmma::load_matrix_sync(ones, s_one, 16);
            const int nt = wid;
            FragC c[MTMAX];
            for (int m = 0; m < mt; ++m) wmma::fill_fragment(c[m], 0.0f);
            uint4 nb = g_wp_f[nt * 32 + lane];
            for (int ks = 0; ks < 24; ++ks) {
                FragBR bw;
                expand_b(bw, nb);
                nb = g_wp_f[((ks + 1) * 12 + nt) * 32 + lane];
                for (int m = 0; m < mt; ++m) {
                    FragA a;
                    wmma::load_matrix_sync(a, s_qp + m * 16 * SQP + ks * 16, SQP);
                    wmma::mma_sync(c[m], a, bw, c[m]);
                }
            }
            {
                FragBR bw;
                expand_b(bw, nb);
                for (int m = 0; m < mt; ++m) wmma::mma_sync(c[m], ones, bw, c[m]);
            }
            if (nr == CHUNK) {
                float* dst = out + (size_t)b * QN_ * CQ_ + (size_t)q0 * CQ_ + nt * 16;
                for (int m = 0; m < mt; ++m)
                    wmma::store_matrix_sync(dst + m * 16 * CQ_, c[m], CQ_, wmma::mem_row_major);
            } else {
                for (int m = 0; m < mt; ++m)
                    wmma::store_matrix_sync(s_ost + m * 16 * CQ_ + nt * 16, c[m],
                                            CQ_, wmma::mem_row_major);
            }
        }
        if (nr != CHUNK) {
            __syncthreads();
            float4* ob = (float4*)(out + (size_t)b * QN_ * CQ_ + (size_t)q0 * CQ_);
            for (int i = tid; i < nr * 48; i += NT) ob[i] = ((float4*)s_ost)[i];
        }
        __syncthreads();
    }
}

extern "C" void kernel_launch(void* const* d_in, const int* in_sizes, int n_in,
                              void* d_out, int out_size) {
    const float* kv         = (const float*)d_in[0];
    const float* q          = (const float*)d_in[1];
    const float* w_kv       = (const float*)d_in[2];
    const float* b_kv       = (const float*)d_in[3];
    const float* w_q        = (const float*)d_in[4];
    const float* b_q        = (const float*)d_in[5];
    const float* bias_table = (const float*)d_in[6];
    const float* w_proj     = (const float*)d_in[7];
    const float* b_proj     = (const float*)d_in[8];
    float* out = (float*)d_out;

    const int B = in_sizes[0] / (NKEY * DIM_);              // 2048
    const int nfrag = NF_KV + NF_Q + NF_P;                  // 1812
    pack_frags<<<(nfrag + 7) / 8, 256>>>(w_kv, b_kv, w_q, b_q, w_proj, b_proj);
    pack_bias<<<(NH_ * 49 * NKEY + 511) / 512, 512>>>(bias_table);

    cudaFuncSetAttribute(wca_kernel, cudaFuncAttributeMaxDynamicSharedMemorySize, SMEM_BYTES);
    wca_kernel<<<B, NT, SMEM_BYTES>>>(kv, q, out);
}

// round 10
// speedup vs baseline: 1.0337x; 1.0337x over previous
#include <cuda_runtime.h>
#include <cuda_fp16.h>
#include <mma.h>
#include <cstdint>

using namespace nvcuda;

namespace {
constexpr int NKEY = 49;
constexpr int QN_  = 196;
constexpr int DIM_ = 384;
constexpr int NH_  = 12;
constexpr int HD_  = 32;
constexpr int CQ_  = 192;
constexpr float SCALE_ = 0.17677669529663687f;

constexpr int NT    = 384;   // 12 warps
constexpr int NW    = 12;
constexpr int CHUNK = 64;
constexpr int MTMAX = 4;
constexpr int NKP   = 64;

constexpr int SKVH = 392;    // K/V row stride (halves)
constexpr int SQP  = 392;    // qp / x row stride (halves)
constexpr int SQIN = 200;    // q-input row stride (halves)
constexpr int STGF = 68;     // attention staging stride (f32)
constexpr int QSTG = 40;     // warp-local Q staging stride (halves)

// smem byte offsets
constexpr int OFF_K   = 0;                          // 64*392*2 = 50176
constexpr int OFF_V   = 50176;
constexpr int OFF_SCR = 100352;                     // qin 64x200 half / ost 16x192 f32
constexpr int OFF_QP  = 125952;                     // 64x392 half (phase1: s_x)
constexpr int OFF_STG = 176128;                     // 12 * 16*68*4 = 52224
constexpr int OFF_QC  = 228352;                     // 196 ints
constexpr int OFF_ONE = 229136;
constexpr int SMEM_BYTES = 229648;

using FragA  = wmma::fragment<wmma::matrix_a, 16, 16, 16, __half, wmma::row_major>;
using FragBR = wmma::fragment<wmma::matrix_b, 16, 16, 16, __half, wmma::row_major>;
using FragBC = wmma::fragment<wmma::matrix_b, 16, 16, 16, __half, wmma::col_major>;
using FragC  = wmma::fragment<wmma::accumulator, 16, 16, 16, float>;
using FragCH = wmma::fragment<wmma::accumulator, 16, 16, 16, __half>;

constexpr int NF_KV = 25 * 48;
constexpr int NF_Q  = 13 * 24;
constexpr int NF_P  = 25 * 12;
}

__device__ uint4 g_wkv_f[NF_KV * 32];
__device__ uint4 g_wq_f [NF_Q  * 32];
__device__ uint4 g_wp_f [NF_P  * 32];
__device__ float g_bias_f[NH_ * 49 * NKEY];

__device__ __forceinline__ void expand_b(FragBR& f, uint4 v) {
    unsigned int w[4] = {v.x, v.y, v.z, v.w};
#pragma unroll
    for (int i = 0; i < 4; ++i) {
        const __half2 h2 = *reinterpret_cast<const __half2*>(&w[i]);
        f.x[2 * i]     = __low2half(h2);
        f.x[2 * i + 1] = __high2half(h2);
    }
}

__device__ __forceinline__ void cvt_store_half(__half* dst, int ld, const FragC& c) {
    FragCH h;
#pragma unroll
    for (int i = 0; i < 8; ++i) h.x[i] = __float2half_rn(c.x[i]);
    wmma::store_matrix_sync(dst, h, ld, wmma::mem_row_major);
}

// ---------------- setup kernels ----------------
__global__ void pack_frags(const float* __restrict__ w_kv, const float* __restrict__ b_kv,
                           const float* __restrict__ w_q,  const float* __restrict__ b_q,
                           const float* __restrict__ w_proj, const float* __restrict__ b_proj) {
    __shared__ __half tiles[8][256];
    const int w    = blockIdx.x * 8 + (threadIdx.x >> 5);
    const int lane = threadIdx.x & 31;
    __half* tile = tiles[threadIdx.x >> 5];
    uint4* dst;
    if (w < NF_KV) {
        const int ks = w / 48, nt = w - ks * 48, n0 = nt * 16;
        for (int e = lane; e < 256; e += 32) {
            const int r = e >> 4, c = e & 15;
            float v;
            if (ks < 24) v = w_kv[(ks * 16 + r) * 768 + n0 + c];
            else         v = (r == 0) ? b_kv[n0 + c] : 0.0f;
            tile[e] = __float2half_rn(v);
        }
        dst = g_wkv_f + w * 32;
    } else if (w < NF_KV + NF_Q) {
        const int w2 = w - NF_KV, ks = w2 / 24, nt = w2 - ks * 24, n0 = nt * 16;
        for (int e = lane; e < 256; e += 32) {
            const int r = e >> 4, c = e & 15;
            float v;
            if (ks < 12) v = w_q[(ks * 16 + r) * DIM_ + n0 + c] * SCALE_;
            else         v = (r == 0) ? b_q[n0 + c] * SCALE_ : 0.0f;
            tile[e] = __float2half_rn(v);
        }
        dst = g_wq_f + w2 * 32;
    } else if (w < NF_KV + NF_Q + NF_P) {
        const int w3 = w - NF_KV - NF_Q, ks = w3 / 12, nt = w3 - ks * 12, n0 = nt * 16;
        for (int e = lane; e < 256; e += 32) {
            const int r = e >> 4, c = e & 15;
            float v;
            if (ks < 24) v = w_proj[(ks * 16 + r) * CQ_ + n0 + c];
            else         v = (r == 0) ? b_proj[n0 + c] : 0.0f;
            tile[e] = __float2half_rn(v);
        }
        dst = g_wp_f + w3 * 32;
    } else return;
    __syncwarp();
    FragBR f;
    wmma::load_matrix_sync(f, tile, 16);
    unsigned int w4[4];
#pragma unroll
    for (int i = 0; i < 4; ++i) {
        __half2 h2 = __halves2half2(f.x[2 * i], f.x[2 * i + 1]);
        w4[i] = *reinterpret_cast<unsigned int*>(&h2);
    }
    dst[lane] = make_uint4(w4[0], w4[1], w4[2], w4[3]);
}

__global__ void pack_bias(const float* __restrict__ bias_table) {
    const int idx = blockIdx.x * blockDim.x + threadIdx.x;
    if (idx >= NH_ * 49 * NKEY) return;
    const int h   = idx / (49 * NKEY);
    const int rem = idx - h * 49 * NKEY;
    const int qc  = rem / NKEY;
    const int key = rem - qc * NKEY;
    const int qi2 = qc / 7, qj2 = qc - qi2 * 7;
    const int kp  = key * 4;
    const int ki  = kp / 14, kj = kp - ki * 14;
    const int dh  = qi2 - (ki >> 1) + 6;
    const int dw  = qj2 - (kj >> 1) + 6;
    g_bias_f[idx] = bias_table[(dh * 13 + dw) * NH_ + h];
}

// ---------------- main kernel ----------------
__global__ __launch_bounds__(NT, 1)
void wca_kernel(const float* __restrict__ kv, const float* __restrict__ q,
                float* __restrict__ out)
{
    extern __shared__ char smb[];
    __half* s_k   = (__half*)(smb + OFF_K);
    __half* s_v   = (__half*)(smb + OFF_V);
    __half* s_qin = (__half*)(smb + OFF_SCR);   // 64x200 half
    float*  s_ost = (float*)(smb + OFF_SCR);    // partial chunk: 16x192 f32
    __half* s_qp  = (__half*)(smb + OFF_QP);    // 64x392 half (phase1: s_x)
    __half* s_x   = (__half*)(smb + OFF_QP);
    float*  s_stg = (float*)(smb + OFF_STG);    // 12 x (16x68) f32
    int*    s_qc  = (int*)(smb + OFF_QC);       // 196 bias-cell ids
    __half* s_one = (__half*)(smb + OFF_ONE);

    const int b    = blockIdx.x;
    const int tid  = threadIdx.x;
    const int wid  = tid >> 5;
    const int lane = tid & 31;
    float* wstg = s_stg + wid * (16 * STGF);

    // ---- phase 0 ----
    {
        const float4* src = (const float4*)(kv + (size_t)b * NKEY * DIM_);
        for (int i = tid; i < NKEY * 96; i += NT) {
            const int r = i / 96, c4 = (i - r * 96) * 4;
            const float4 v = src[i];
            __half* d = s_x + r * SQP + c4;
            d[0] = __float2half_rn(v.x); d[1] = __float2half_rn(v.y);
            d[2] = __float2half_rn(v.z); d[3] = __float2half_rn(v.w);
        }
        for (int i = tid; i < (NKP - NKEY) * SQP; i += NT)
            s_x[NKEY * SQP + i] = __float2half_rn(0.0f);
        if (tid < 256) s_one[tid] = __float2half_rn((tid & 15) == 0 ? 1.0f : 0.0f);
        if (tid < QN_) {
            const int qi = tid / 14, qj = tid - qi * 14;
            s_qc[tid] = (qi >> 1) * 7 + (qj >> 1);
        }
    }
    __syncthreads();

    // ---- phase 1: kv projection, B-stationary over 4 m-tiles ----
    {
        FragA ones;
        wmma::load_matrix_sync(ones, s_one, 16);
        for (int j = 0; j < 2; ++j) {
            const int nt0 = (wid * 2 + j) * 2;
            FragC c[4][2];
#pragma unroll
            for (int m = 0; m < 4; ++m) {
                wmma::fill_fragment(c[m][0], 0.0f);
                wmma::fill_fragment(c[m][1], 0.0f);
            }
            uint4 nb0 = g_wkv_f[nt0 * 32 + lane];
            uint4 nb1 = g_wkv_f[(nt0 + 1) * 32 + lane];
            for (int ks = 0; ks < 24; ++ks) {
                FragBR b0, b1;
                expand_b(b0, nb0);
                expand_b(b1, nb1);
                nb0 = g_wkv_f[((ks + 1) * 48 + nt0) * 32 + lane];
                nb1 = g_wkv_f[((ks + 1) * 48 + nt0 + 1) * 32 + lane];
#pragma unroll
                for (int m = 0; m < 4; ++m) {
                    FragA a;
                    wmma::load_matrix_sync(a, s_x + m * 16 * SQP + ks * 16, SQP);
                    wmma::mma_sync(c[m][0], a, b0, c[m][0]);
                    wmma::mma_sync(c[m][1], a, b1, c[m][1]);
                }
            }
            {
                FragBR b0, b1;
                expand_b(b0, nb0);
                expand_b(b1, nb1);
#pragma unroll
                for (int m = 0; m < 4; ++m) {
                    wmma::mma_sync(c[m][0], ones, b0, c[m][0]);
                    wmma::mma_sync(c[m][1], ones, b1, c[m][1]);
                }
            }
#pragma unroll
            for (int t = 0; t < 2; ++t) {
                const int colg = (nt0 + t) * 16;
                __half* dst = (colg < DIM_) ? (s_k + colg) : (s_v + colg - DIM_);
#pragma unroll
                for (int m = 0; m < 4; ++m)
                    cvt_store_half(dst + m * 16 * SKVH, SKVH, c[m][t]);
            }
        }
    }
    __syncthreads();

    // ---- phase 2: q chunks of 64 rows; q-proj fused into per-head warp ----
    for (int q0 = 0; q0 < QN_; q0 += CHUNK) {
        const int nr = min(CHUNK, QN_ - q0);
        const int mt = (nr + 15) >> 4;

        // 2a: q chunk -> half (zero pad to mt*16 rows)
        {
            const float4* src = (const float4*)(q + (size_t)b * QN_ * CQ_ + (size_t)q0 * CQ_);
            for (int i = tid; i < mt * 16 * 48; i += NT) {
                const int r = i / 48, c4 = (i - r * 48) * 4;
                float4 v = make_float4(0.f, 0.f, 0.f, 0.f);
                if (r < nr) v = src[i];
                __half* d = s_qin + r * SQIN + c4;
                d[0] = __float2half_rn(v.x); d[1] = __float2half_rn(v.y);
                d[2] = __float2half_rn(v.z); d[3] = __float2half_rn(v.w);
            }
        }
        __syncthreads();

        // 2b+2c fused: warp = head h; q-proj for head cols, then attention
        {
            const int h = wid;
            const int base = h * HD_;
            const int nt0 = h * 2;
            FragA ones;
            wmma::load_matrix_sync(ones, s_one, 16);

            FragC qc[MTMAX][2];
#pragma unroll
            for (int m = 0; m < MTMAX; ++m) if (m < mt) {
                wmma::fill_fragment(qc[m][0], 0.0f);
                wmma::fill_fragment(qc[m][1], 0.0f);
            }
            uint4 nb0 = g_wq_f[nt0 * 32 + lane];
            uint4 nb1 = g_wq_f[(nt0 + 1) * 32 + lane];
            for (int ks = 0; ks < 12; ++ks) {
                FragBR b0, b1;
                expand_b(b0, nb0);
                expand_b(b1, nb1);
                nb0 = g_wq_f[((ks + 1) * 24 + nt0) * 32 + lane];
                nb1 = g_wq_f[((ks + 1) * 24 + nt0 + 1) * 32 + lane];
#pragma unroll
                for (int m = 0; m < MTMAX; ++m) if (m < mt) {
                    FragA a;
                    wmma::load_matrix_sync(a, s_qin + m * 16 * SQIN + ks * 16, SQIN);
                    wmma::mma_sync(qc[m][0], a, b0, qc[m][0]);
                    wmma::mma_sync(qc[m][1], a, b1, qc[m][1]);
                }
            }
            {
                FragBR b0, b1;
                expand_b(b0, nb0);
                expand_b(b1, nb1);
#pragma unroll
                for (int m = 0; m < MTMAX; ++m) if (m < mt) {
                    wmma::mma_sync(qc[m][0], ones, b0, qc[m][0]);
                    wmma::mma_sync(qc[m][1], ones, b1, qc[m][1]);
                }
            }

            __half* qstg = (__half*)wstg;          // warp-local Q staging, stride 40
#pragma unroll
            for (int s = 0; s < MTMAX; ++s) if (s < mt) {
                cvt_store_half(qstg,      QSTG, qc[s][0]);
                cvt_store_half(qstg + 16, QSTG, qc[s][1]);
                __syncwarp();

                // S = Q_h K_h^T over 64 padded keys
                FragC sf[4];
#pragma unroll
                for (int t = 0; t < 4; ++t) wmma::fill_fragment(sf[t], 0.0f);
#pragma unroll
                for (int ks = 0; ks < 2; ++ks) {
                    FragA a;
                    wmma::load_matrix_sync(a, qstg + ks * 16, QSTG);
#pragma unroll
                    for (int t = 0; t < 4; ++t) {
                        FragBC bk;
                        wmma::load_matrix_sync(bk, s_k + (t * 16) * SKVH + base + ks * 16, SKVH);
                        wmma::mma_sync(sf[t], a, bk, sf[t]);
                    }
                }
#pragma unroll
                for (int t = 0; t < 4; ++t)
                    wmma::store_matrix_sync(wstg + t * 16, sf[t], STGF, wmma::mem_row_major);
                __syncwarp();

                // softmax, 2 lanes/row; all-register vals; pre-normalized half P
                {
                    const int r = lane >> 1, par = lane & 1;
                    float* row = wstg + r * STGF;
                    const float* brow =
                        g_bias_f + (h * 49 + s_qc[min(q0 + s * 16 + r, QN_ - 1)]) * NKEY;
                    float vals[25];
                    float mx = -1e30f;
#pragma unroll
                    for (int i = 0; i < 25; ++i) {
                        const int c = par + 2 * i;
                        float v = -1e30f;
                        if (c < NKEY) v = row[c] + brow[c];
                        vals[i] = v;
                        mx = fmaxf(mx, v);
                    }
                    mx = fmaxf(mx, __shfl_xor_sync(0xffffffffu, mx, 1));
                    float ssum = 0.f;
#pragma unroll
                    for (int i = 0; i < 25; ++i) {
                        const int c = par + 2 * i;
                        const float p = (c < NKEY) ? __expf(vals[i] - mx) : 0.0f;
                        vals[i] = p;
                        ssum += p;
                    }
                    ssum += __shfl_xor_sync(0xffffffffu, ssum, 1);
                    const float inv = 1.0f / ssum;
                    __half* prow = (__half*)wstg + r * (STGF * 2);
#pragma unroll
                    for (int i = 0; i < 25; ++i) {
                        const int c = par + 2 * i;
                        prow[c] = __float2half_rn(vals[i] * inv);
                    }
#pragma unroll
                    for (int i = 25; i < 32; ++i) {
                        const int c = par + 2 * i;
                        if (c < 64) prow[c] = __float2half_rn(0.0f);
                    }
                }
                __syncwarp();

                // O = Pn V over 64 keys; direct half store into s_qp
                FragC o[2];
                wmma::fill_fragment(o[0], 0.0f);
                wmma::fill_fragment(o[1], 0.0f);
#pragma unroll
                for (int ks = 0; ks < 4; ++ks) {
                    FragA a;
                    wmma::load_matrix_sync(a, (__half*)wstg + ks * 16, STGF * 2);
#pragma unroll
                    for (int t = 0; t < 2; ++t) {
                        FragBR bv;
                        wmma::load_matrix_sync(bv, s_v + ks * 16 * SKVH + base + t * 16, SKVH);
                        wmma::mma_sync(o[t], a, bv, o[t]);
                    }
                }
#pragma unroll
                for (int t = 0; t < 2; ++t)
                    cvt_store_half(s_qp + s * 16 * SQP + base + t * 16, SQP, o[t]);
                __syncwarp();
            }
        }
        __syncthreads();

        // 2d: out projection — warp = 1 n-tile x mt m-tiles
        {
            FragA ones;
            wmma::load_matrix_sync(ones, s_one, 16);
            const int nt = wid;
            FragC c[MTMAX];
#pragma unroll
            for (int m = 0; m < MTMAX; ++m) if (m < mt) wmma::fill_fragment(c[m], 0.0f);
            uint4 nb = g_wp_f[nt * 32 + lane];
            for (int ks = 0; ks < 24; ++ks) {
                FragBR bw;
                expand_b(bw, nb);
                nb = g_wp_f[((ks + 1) * 12 + nt) * 32 + lane];
#pragma unroll
                for (int m = 0; m < MTMAX; ++m) if (m < mt) {
                    FragA a;
                    wmma::load_matrix_sync(a, s_qp + m * 16 * SQP + ks * 16, SQP);
                    wmma::mma_sync(c[m], a, bw, c[m]);
                }
            }
            {
                FragBR bw;
                expand_b(bw, nb);
#pragma unroll
                for (int m = 0; m < MTMAX; ++m) if (m < mt)
                    wmma::mma_sync(c[m], ones, bw, c[m]);
            }
            if (nr == CHUNK) {
                float* dst = out + (size_t)b * QN_ * CQ_ + (size_t)q0 * CQ_ + nt * 16;
#pragma unroll
                for (int m = 0; m < MTMAX; ++m) if (m < mt)
                    wmma::store_matrix_sync(dst + m * 16 * CQ_, c[m], CQ_, wmma::mem_row_major);
            } else {
#pragma unroll
                for (int m = 0; m < MTMAX; ++m) if (m < mt)
                    wmma::store_matrix_sync(s_ost + m * 16 * CQ_ + nt * 16, c[m],
                                            CQ_, wmma::mem_row_major);
            }
        }
        if (nr != CHUNK) {
            __syncthreads();
            float4* ob = (float4*)(out + (size_t)b * QN_ * CQ_ + (size_t)q0 * CQ_);
            for (int i = tid; i < nr * 48; i += NT) ob[i] = ((float4*)s_ost)[i];
        }
        // no end-of-chunk barrier needed: next 2a writes s_qin, which no 2d reader touches
    }
}

extern "C" void kernel_launch(void* const* d_in, const int* in_sizes, int n_in,
                              void* d_out, int out_size) {
    const float* kv         = (const float*)d_in[0];
    const float* q          = (const float*)d_in[1];
    const float* w_kv       = (const float*)d_in[2];
    const float* b_kv       = (const float*)d_in[3];
    const float* w_q        = (const float*)d_in[4];
    const float* b_q        = (const float*)d_in[5];
    const float* bias_table = (const float*)d_in[6];
    const float* w_proj     = (const float*)d_in[7];
    const float* b_proj     = (const float*)d_in[8];
    float* out = (float*)d_out;

    const int B = in_sizes[0] / (NKEY * DIM_);              // 2048
    const int nfrag = NF_KV + NF_Q + NF_P;                  // 1812
    pack_frags<<<(nfrag + 7) / 8, 256>>>(w_kv, b_kv, w_q, b_q, w_proj, b_proj);
    pack_bias<<<(NH_ * 49 * NKEY + 511) / 512, 512>>>(bias_table);

    cudaFuncSetAttribute(wca_kernel, cudaFuncAttributeMaxDynamicSharedMemorySize, SMEM_BYTES);
    wca_kernel<<<B, NT, SMEM_BYTES>>>(kv, q, out);
}

// round 11
// speedup vs baseline: 1.1888x; 1.1500x over previous
#include <cuda_runtime.h>
#include <cuda_fp16.h>
#include <mma.h>
#include <cstdint>

using namespace nvcuda;

namespace {
constexpr int NKEY = 49;
constexpr int QN_  = 196;
constexpr int DIM_ = 384;
constexpr int NH_  = 12;
constexpr int HD_  = 32;
constexpr int CQ_  = 192;
constexpr float SCALE_ = 0.17677669529663687f;

constexpr int NT    = 384;   // 12 warps
constexpr int NW    = 12;
constexpr int CHUNK = 64;
constexpr int MTMAX = 4;
constexpr int NKP   = 64;

constexpr int SKVH = 392;    // K/V row stride (halves)
constexpr int SQP  = 392;    // qp / x row stride (halves)
constexpr int SQIN = 200;    // q-input row stride (halves)

// smem byte offsets (no attention staging anymore)
constexpr int OFF_K   = 0;                          // 64*392*2 = 50176
constexpr int OFF_V   = 50176;
constexpr int OFF_SCR = 100352;                     // qin 64x200 half / ost 16x192 f32
constexpr int OFF_QP  = 125952;                     // 64x392 half (phase1: s_x)
constexpr int OFF_QC  = 176128;                     // 196 ints
constexpr int OFF_ONE = 176912;
constexpr int SMEM_BYTES = 177424;

using FragA  = wmma::fragment<wmma::matrix_a, 16, 16, 16, __half, wmma::row_major>;
using FragBR = wmma::fragment<wmma::matrix_b, 16, 16, 16, __half, wmma::row_major>;
using FragBC = wmma::fragment<wmma::matrix_b, 16, 16, 16, __half, wmma::col_major>;
using FragC  = wmma::fragment<wmma::accumulator, 16, 16, 16, float>;
using FragCH = wmma::fragment<wmma::accumulator, 16, 16, 16, __half>;

constexpr int NF_KV = 25 * 48;
constexpr int NF_Q  = 13 * 24;
constexpr int NF_P  = 25 * 12;
}

__device__ uint4 g_wkv_f[NF_KV * 32];
__device__ uint4 g_wq_f [NF_Q  * 32];
__device__ uint4 g_wp_f [NF_P  * 32];
__device__ float g_bias_f[NH_ * 49 * NKEY];

__device__ __forceinline__ void expand_b(FragBR& f, uint4 v) {
    unsigned int w[4] = {v.x, v.y, v.z, v.w};
#pragma unroll
    for (int i = 0; i < 4; ++i) {
        const __half2 h2 = *reinterpret_cast<const __half2*>(&w[i]);
        f.x[2 * i]     = __low2half(h2);
        f.x[2 * i + 1] = __high2half(h2);
    }
}

__device__ __forceinline__ void cvt_store_half(__half* dst, int ld, const FragC& c) {
    FragCH h;
#pragma unroll
    for (int i = 0; i < 8; ++i) h.x[i] = __float2half_rn(c.x[i]);
    wmma::store_matrix_sync(dst, h, ld, wmma::mem_row_major);
}

// f32 accumulator fragment -> row-major half A fragment (same element map)
__device__ __forceinline__ void cvt_acc_to_a(FragA& a, const FragC& c) {
#pragma unroll
    for (int i = 0; i < 8; ++i) a.x[i] = __float2half_rn(c.x[i]);
}

// ---------------- setup kernels ----------------
__global__ void pack_frags(const float* __restrict__ w_kv, const float* __restrict__ b_kv,
                           const float* __restrict__ w_q,  const float* __restrict__ b_q,
                           const float* __restrict__ w_proj, const float* __restrict__ b_proj) {
    __shared__ __half tiles[8][256];
    const int w    = blockIdx.x * 8 + (threadIdx.x >> 5);
    const int lane = threadIdx.x & 31;
    __half* tile = tiles[threadIdx.x >> 5];
    uint4* dst;
    if (w < NF_KV) {
        const int ks = w / 48, nt = w - ks * 48, n0 = nt * 16;
        for (int e = lane; e < 256; e += 32) {
            const int r = e >> 4, c = e & 15;
            float v;
            if (ks < 24) v = w_kv[(ks * 16 + r) * 768 + n0 + c];
            else         v = (r == 0) ? b_kv[n0 + c] : 0.0f;
            tile[e] = __float2half_rn(v);
        }
        dst = g_wkv_f + w * 32;
    } else if (w < NF_KV + NF_Q) {
        const int w2 = w - NF_KV, ks = w2 / 24, nt = w2 - ks * 24, n0 = nt * 16;
        for (int e = lane; e < 256; e += 32) {
            const int r = e >> 4, c = e & 15;
            float v;
            if (ks < 12) v = w_q[(ks * 16 + r) * DIM_ + n0 + c] * SCALE_;
            else         v = (r == 0) ? b_q[n0 + c] * SCALE_ : 0.0f;
            tile[e] = __float2half_rn(v);
        }
        dst = g_wq_f + w2 * 32;
    } else if (w < NF_KV + NF_Q + NF_P) {
        const int w3 = w - NF_KV - NF_Q, ks = w3 / 12, nt = w3 - ks * 12, n0 = nt * 16;
        for (int e = lane; e < 256; e += 32) {
            const int r = e >> 4, c = e & 15;
            float v;
            if (ks < 24) v = w_proj[(ks * 16 + r) * CQ_ + n0 + c];
            else         v = (r == 0) ? b_proj[n0 + c] : 0.0f;
            tile[e] = __float2half_rn(v);
        }
        dst = g_wp_f + w3 * 32;
    } else return;
    __syncwarp();
    FragBR f;
    wmma::load_matrix_sync(f, tile, 16);
    unsigned int w4[4];
#pragma unroll
    for (int i = 0; i < 4; ++i) {
        __half2 h2 = __halves2half2(f.x[2 * i], f.x[2 * i + 1]);
        w4[i] = *reinterpret_cast<unsigned int*>(&h2);
    }
    dst[lane] = make_uint4(w4[0], w4[1], w4[2], w4[3]);
}

__global__ void pack_bias(const float* __restrict__ bias_table) {
    const int idx = blockIdx.x * blockDim.x + threadIdx.x;
    if (idx >= NH_ * 49 * NKEY) return;
    const int h   = idx / (49 * NKEY);
    const int rem = idx - h * 49 * NKEY;
    const int qc  = rem / NKEY;
    const int key = rem - qc * NKEY;
    const int qi2 = qc / 7, qj2 = qc - qi2 * 7;
    const int kp  = key * 4;
    const int ki  = kp / 14, kj = kp - ki * 14;
    const int dh  = qi2 - (ki >> 1) + 6;
    const int dw  = qj2 - (kj >> 1) + 6;
    g_bias_f[idx] = bias_table[(dh * 13 + dw) * NH_ + h];
}

// ---------------- main kernel ----------------
__global__ __launch_bounds__(NT, 1)
void wca_kernel(const float* __restrict__ kv, const float* __restrict__ q,
                float* __restrict__ out)
{
    extern __shared__ char smb[];
    __half* s_k   = (__half*)(smb + OFF_K);
    __half* s_v   = (__half*)(smb + OFF_V);
    __half* s_qin = (__half*)(smb + OFF_SCR);   // 64x200 half
    float*  s_ost = (float*)(smb + OFF_SCR);    // partial chunk: 16x192 f32
    __half* s_qp  = (__half*)(smb + OFF_QP);    // 64x392 half (phase1: s_x)
    __half* s_x   = (__half*)(smb + OFF_QP);
    int*    s_qc  = (int*)(smb + OFF_QC);       // 196 bias-cell ids
    __half* s_one = (__half*)(smb + OFF_ONE);

    const int b    = blockIdx.x;
    const int tid  = threadIdx.x;
    const int wid  = tid >> 5;
    const int lane = tid & 31;

    // ---- phase 0 ----
    {
        const float4* src = (const float4*)(kv + (size_t)b * NKEY * DIM_);
        for (int i = tid; i < NKEY * 96; i += NT) {
            const int r = i / 96, c4 = (i - r * 96) * 4;
            const float4 v = src[i];
            __half* d = s_x + r * SQP + c4;
            d[0] = __float2half_rn(v.x); d[1] = __float2half_rn(v.y);
            d[2] = __float2half_rn(v.z); d[3] = __float2half_rn(v.w);
        }
        for (int i = tid; i < (NKP - NKEY) * SQP; i += NT)
            s_x[NKEY * SQP + i] = __float2half_rn(0.0f);
        if (tid < 256) s_one[tid] = __float2half_rn((tid & 15) == 0 ? 1.0f : 0.0f);
        if (tid < QN_) {
            const int qi = tid / 14, qj = tid - qi * 14;
            s_qc[tid] = (qi >> 1) * 7 + (qj >> 1);
        }
    }
    __syncthreads();

    // ---- phase 1: kv projection, B-stationary over 4 m-tiles ----
    {
        FragA ones;
        wmma::load_matrix_sync(ones, s_one, 16);
        for (int j = 0; j < 2; ++j) {
            const int nt0 = (wid * 2 + j) * 2;
            FragC c[4][2];
#pragma unroll
            for (int m = 0; m < 4; ++m) {
                wmma::fill_fragment(c[m][0], 0.0f);
                wmma::fill_fragment(c[m][1], 0.0f);
            }
            uint4 nb0 = g_wkv_f[nt0 * 32 + lane];
            uint4 nb1 = g_wkv_f[(nt0 + 1) * 32 + lane];
            for (int ks = 0; ks < 24; ++ks) {
                FragBR b0, b1;
                expand_b(b0, nb0);
                expand_b(b1, nb1);
                nb0 = g_wkv_f[((ks + 1) * 48 + nt0) * 32 + lane];
                nb1 = g_wkv_f[((ks + 1) * 48 + nt0 + 1) * 32 + lane];
#pragma unroll
                for (int m = 0; m < 4; ++m) {
                    FragA a;
                    wmma::load_matrix_sync(a, s_x + m * 16 * SQP + ks * 16, SQP);
                    wmma::mma_sync(c[m][0], a, b0, c[m][0]);
                    wmma::mma_sync(c[m][1], a, b1, c[m][1]);
                }
            }
            {
                FragBR b0, b1;
                expand_b(b0, nb0);
                expand_b(b1, nb1);
#pragma unroll
                for (int m = 0; m < 4; ++m) {
                    wmma::mma_sync(c[m][0], ones, b0, c[m][0]);
                    wmma::mma_sync(c[m][1], ones, b1, c[m][1]);
                }
            }
#pragma unroll
            for (int t = 0; t < 2; ++t) {
                const int colg = (nt0 + t) * 16;
                __half* dst = (colg < DIM_) ? (s_k + colg) : (s_v + colg - DIM_);
#pragma unroll
                for (int m = 0; m < 4; ++m)
                    cvt_store_half(dst + m * 16 * SKVH, SKVH, c[m][t]);
            }
        }
    }
    __syncthreads();

    // ---- phase 2: q chunks of 64 rows; fully register-resident attention ----
    for (int q0 = 0; q0 < QN_; q0 += CHUNK) {
        const int nr = min(CHUNK, QN_ - q0);
        const int mt = (nr + 15) >> 4;

        // 2a: q chunk -> half (zero pad to mt*16 rows)
        {
            const float4* src = (const float4*)(q + (size_t)b * QN_ * CQ_ + (size_t)q0 * CQ_);
            for (int i = tid; i < mt * 16 * 48; i += NT) {
                const int r = i / 48, c4 = (i - r * 48) * 4;
                float4 v = make_float4(0.f, 0.f, 0.f, 0.f);
                if (r < nr) v = src[i];
                __half* d = s_qin + r * SQIN + c4;
                d[0] = __float2half_rn(v.x); d[1] = __float2half_rn(v.y);
                d[2] = __float2half_rn(v.z); d[3] = __float2half_rn(v.w);
            }
        }
        __syncthreads();

        // 2b+2c fused: warp = head h
        {
            const int h = wid;
            const int base = h * HD_;
            const int nt0 = h * 2;
            const int r0l = lane >> 2;            // fragment row (lane quad)
            const int c0l = (lane & 3) * 2;       // fragment col base
            FragA ones;
            wmma::load_matrix_sync(ones, s_one, 16);

            // q projection -> qc[m][2] (head cols base..base+31)
            FragC qc[MTMAX][2];
#pragma unroll
            for (int m = 0; m < MTMAX; ++m) if (m < mt) {
                wmma::fill_fragment(qc[m][0], 0.0f);
                wmma::fill_fragment(qc[m][1], 0.0f);
            }
            uint4 nb0 = g_wq_f[nt0 * 32 + lane];
            uint4 nb1 = g_wq_f[(nt0 + 1) * 32 + lane];
            for (int ks = 0; ks < 12; ++ks) {
                FragBR b0, b1;
                expand_b(b0, nb0);
                expand_b(b1, nb1);
                nb0 = g_wq_f[((ks + 1) * 24 + nt0) * 32 + lane];
                nb1 = g_wq_f[((ks + 1) * 24 + nt0 + 1) * 32 + lane];
#pragma unroll
                for (int m = 0; m < MTMAX; ++m) if (m < mt) {
                    FragA a;
                    wmma::load_matrix_sync(a, s_qin + m * 16 * SQIN + ks * 16, SQIN);
                    wmma::mma_sync(qc[m][0], a, b0, qc[m][0]);
                    wmma::mma_sync(qc[m][1], a, b1, qc[m][1]);
                }
            }
            {
                FragBR b0, b1;
                expand_b(b0, nb0);
                expand_b(b1, nb1);
#pragma unroll
                for (int m = 0; m < MTMAX; ++m) if (m < mt) {
                    wmma::mma_sync(qc[m][0], ones, b0, qc[m][0]);
                    wmma::mma_sync(qc[m][1], ones, b1, qc[m][1]);
                }
            }
            // convert Q accumulators to A fragments (same element map)
            FragA qa[MTMAX][2];
#pragma unroll
            for (int m = 0; m < MTMAX; ++m) if (m < mt) {
                cvt_acc_to_a(qa[m][0], qc[m][0]);
                cvt_acc_to_a(qa[m][1], qc[m][1]);
            }

#pragma unroll
            for (int s = 0; s < MTMAX; ++s) if (s < mt) {
                // S = Q_h K_h^T over 64 padded keys (all in registers)
                FragC sf[4];
#pragma unroll
                for (int t = 0; t < 4; ++t) wmma::fill_fragment(sf[t], 0.0f);
#pragma unroll
                for (int ks = 0; ks < 2; ++ks) {
#pragma unroll
                    for (int t = 0; t < 4; ++t) {
                        FragBC bk;
                        wmma::load_matrix_sync(bk, s_k + (t * 16) * SKVH + base + ks * 16, SKVH);
                        wmma::mma_sync(sf[t], qa[s][ks], bk, sf[t]);
                    }
                }

                // in-register softmax (rows r0l and r0l+8 of this 16-row tile)
                const float* bias0 =
                    g_bias_f + (h * 49 + s_qc[min(q0 + s * 16 + r0l, QN_ - 1)]) * NKEY;
                const float* bias1 =
                    g_bias_f + (h * 49 + s_qc[min(q0 + s * 16 + r0l + 8, QN_ - 1)]) * NKEY;
                float mx0 = -1e30f, mx1 = -1e30f;
#pragma unroll
                for (int t = 0; t < 4; ++t) {
                    const int cb = t * 16 + c0l;
                    float v;
                    v = (cb     < NKEY) ? sf[t].x[0] + bias0[cb]     : -1e30f; sf[t].x[0] = v; mx0 = fmaxf(mx0, v);
                    v = (cb + 1 < NKEY) ? sf[t].x[1] + bias0[cb + 1] : -1e30f; sf[t].x[1] = v; mx0 = fmaxf(mx0, v);
                    v = (cb + 8 < NKEY) ? sf[t].x[4] + bias0[cb + 8] : -1e30f; sf[t].x[4] = v; mx0 = fmaxf(mx0, v);
                    v = (cb + 9 < NKEY) ? sf[t].x[5] + bias0[cb + 9] : -1e30f; sf[t].x[5] = v; mx0 = fmaxf(mx0, v);
                    v = (cb     < NKEY) ? sf[t].x[2] + bias1[cb]     : -1e30f; sf[t].x[2] = v; mx1 = fmaxf(mx1, v);
                    v = (cb + 1 < NKEY) ? sf[t].x[3] + bias1[cb + 1] : -1e30f; sf[t].x[3] = v; mx1 = fmaxf(mx1, v);
                    v = (cb + 8 < NKEY) ? sf[t].x[6] + bias1[cb + 8] : -1e30f; sf[t].x[6] = v; mx1 = fmaxf(mx1, v);
                    v = (cb + 9 < NKEY) ? sf[t].x[7] + bias1[cb + 9] : -1e30f; sf[t].x[7] = v; mx1 = fmaxf(mx1, v);
                }
                mx0 = fmaxf(mx0, __shfl_xor_sync(0xffffffffu, mx0, 1));
                mx0 = fmaxf(mx0, __shfl_xor_sync(0xffffffffu, mx0, 2));
                mx1 = fmaxf(mx1, __shfl_xor_sync(0xffffffffu, mx1, 1));
                mx1 = fmaxf(mx1, __shfl_xor_sync(0xffffffffu, mx1, 2));

                float s0 = 0.f, s1 = 0.f;
#pragma unroll
                for (int t = 0; t < 4; ++t) {
                    const int cb = t * 16 + c0l;
                    float p;
                    p = (cb     < NKEY) ? __expf(sf[t].x[0] - mx0) : 0.f; sf[t].x[0] = p; s0 += p;
                    p = (cb + 1 < NKEY) ? __expf(sf[t].x[1] - mx0) : 0.f; sf[t].x[1] = p; s0 += p;
                    p = (cb + 8 < NKEY) ? __expf(sf[t].x[4] - mx0) : 0.f; sf[t].x[4] = p; s0 += p;
                    p = (cb + 9 < NKEY) ? __expf(sf[t].x[5] - mx0) : 0.f; sf[t].x[5] = p; s0 += p;
                    p = (cb     < NKEY) ? __expf(sf[t].x[2] - mx1) : 0.f; sf[t].x[2] = p; s1 += p;
                    p = (cb + 1 < NKEY) ? __expf(sf[t].x[3] - mx1) : 0.f; sf[t].x[3] = p; s1 += p;
                    p = (cb + 8 < NKEY) ? __expf(sf[t].x[6] - mx1) : 0.f; sf[t].x[6] = p; s1 += p;
                    p = (cb + 9 < NKEY) ? __expf(sf[t].x[7] - mx1) : 0.f; sf[t].x[7] = p; s1 += p;
                }
                s0 += __shfl_xor_sync(0xffffffffu, s0, 1);
                s0 += __shfl_xor_sync(0xffffffffu, s0, 2);
                s1 += __shfl_xor_sync(0xffffffffu, s1, 1);
                s1 += __shfl_xor_sync(0xffffffffu, s1, 2);
                const float inv0 = 1.0f / s0;
                const float inv1 = 1.0f / s1;

                // P fragments = PV A fragments (pre-normalized)
                FragA pf[4];
#pragma unroll
                for (int t = 0; t < 4; ++t) {
                    pf[t].x[0] = __float2half_rn(sf[t].x[0] * inv0);
                    pf[t].x[1] = __float2half_rn(sf[t].x[1] * inv0);
                    pf[t].x[4] = __float2half_rn(sf[t].x[4] * inv0);
                    pf[t].x[5] = __float2half_rn(sf[t].x[5] * inv0);
                    pf[t].x[2] = __float2half_rn(sf[t].x[2] * inv1);
                    pf[t].x[3] = __float2half_rn(sf[t].x[3] * inv1);
                    pf[t].x[6] = __float2half_rn(sf[t].x[6] * inv1);
                    pf[t].x[7] = __float2half_rn(sf[t].x[7] * inv1);
                }

                // O = Pn V over 64 keys; direct half store into s_qp
                FragC o[2];
                wmma::fill_fragment(o[0], 0.0f);
                wmma::fill_fragment(o[1], 0.0f);
#pragma unroll
                for (int ks = 0; ks < 4; ++ks) {
#pragma unroll
                    for (int t = 0; t < 2; ++t) {
                        FragBR bv;
                        wmma::load_matrix_sync(bv, s_v + ks * 16 * SKVH + base + t * 16, SKVH);
                        wmma::mma_sync(o[t], pf[ks], bv, o[t]);
                    }
                }
#pragma unroll
                for (int t = 0; t < 2; ++t)
                    cvt_store_half(s_qp + s * 16 * SQP + base + t * 16, SQP, o[t]);
            }
        }
        __syncthreads();

        // 2d: out projection — warp = 1 n-tile x mt m-tiles
        {
            FragA ones;
            wmma::load_matrix_sync(ones, s_one, 16);
            const int nt = wid;
            FragC c[MTMAX];
#pragma unroll
            for (int m = 0; m < MTMAX; ++m) if (m < mt) wmma::fill_fragment(c[m], 0.0f);
            uint4 nb = g_wp_f[nt * 32 + lane];
            for (int ks = 0; ks < 24; ++ks) {
                FragBR bw;
                expand_b(bw, nb);
                nb = g_wp_f[((ks + 1) * 12 + nt) * 32 + lane];
#pragma unroll
                for (int m = 0; m < MTMAX; ++m) if (m < mt) {
                    FragA a;
                    wmma::load_matrix_sync(a, s_qp + m * 16 * SQP + ks * 16, SQP);
                    wmma::mma_sync(c[m], a, bw, c[m]);
                }
            }
            {
                FragBR bw;
                expand_b(bw, nb);
#pragma unroll
                for (int m = 0; m < MTMAX; ++m) if (m < mt)
                    wmma::mma_sync(c[m], ones, bw, c[m]);
            }
            if (nr == CHUNK) {
                float* dst = out + (size_t)b * QN_ * CQ_ + (size_t)q0 * CQ_ + nt * 16;
#pragma unroll
                for (int m = 0; m < MTMAX; ++m) if (m < mt)
                    wmma::store_matrix_sync(dst + m * 16 * CQ_, c[m], CQ_, wmma::mem_row_major);
            } else {
#pragma unroll
                for (int m = 0; m < MTMAX; ++m) if (m < mt)
                    wmma::store_matrix_sync(s_ost + m * 16 * CQ_ + nt * 16, c[m],
                                            CQ_, wmma::mem_row_major);
            }
        }
        if (nr != CHUNK) {
            __syncthreads();
            float4* ob = (float4*)(out + (size_t)b * QN_ * CQ_ + (size_t)q0 * CQ_);
            for (int i = tid; i < nr * 48; i += NT) ob[i] = ((float4*)s_ost)[i];
        }
    }
}

extern "C" void kernel_launch(void* const* d_in, const int* in_sizes, int n_in,
                              void* d_out, int out_size) {
    const float* kv         = (const float*)d_in[0];
    const float* q          = (const float*)d_in[1];
    const float* w_kv       = (const float*)d_in[2];
    const float* b_kv       = (const float*)d_in[3];
    const float* w_q        = (const float*)d_in[4];
    const float* b_q        = (const float*)d_in[5];
    const float* bias_table = (const float*)d_in[6];
    const float* w_proj     = (const float*)d_in[7];
    const float* b_proj     = (const float*)d_in[8];
    float* out = (float*)d_out;

    const int B = in_sizes[0] / (NKEY * DIM_);              // 2048
    const int nfrag = NF_KV + NF_Q + NF_P;                  // 1812
    pack_frags<<<(nfrag + 7) / 8, 256>>>(w_kv, b_kv, w_q, b_q, w_proj, b_proj);
    pack_bias<<<(NH_ * 49 * NKEY + 511) / 512, 512>>>(bias_table);

    cudaFuncSetAttribute(wca_kernel, cudaFuncAttributeMaxDynamicSharedMemorySize, SMEM_BYTES);
    wca_kernel<<<B, NT, SMEM_BYTES>>>(kv, q, out);
}

// round 12
// speedup vs baseline: 1.2669x; 1.0657x over previous
#include <cuda_runtime.h>
#include <cuda_fp16.h>
#include <mma.h>
#include <cstdint>

using namespace nvcuda;

namespace {
constexpr int NKEY = 49;
constexpr int QN_  = 196;
constexpr int DIM_ = 384;
constexpr int NH_  = 12;
constexpr int HD_  = 32;
constexpr int CQ_  = 192;
constexpr float SCALE_ = 0.17677669529663687f;

constexpr int NT    = 384;   // 12 warps
constexpr int NW    = 12;
constexpr int CHUNK = 64;
constexpr int MTMAX = 4;
constexpr int NKP   = 64;
constexpr int NCH   = 4;     // 64+64+64+4

constexpr int SKVH = 392;    // K/V row stride (halves)
constexpr int SQP  = 392;    // qp / x row stride (halves)
constexpr int SQIN = 200;    // q-input row stride (halves)

// smem byte offsets
constexpr int OFF_K   = 0;                // 64*392*2 = 50176
constexpr int OFF_V   = 50176;
constexpr int OFF_SCR = 100352;           // qin 64x200 half (25600) / ost 16x192 f32 (12288)
constexpr int OFF_QP0 = 125952;           // 64x392 half = 50176 (phase1: s_x overlays)
constexpr int OFF_QP1 = 176128;           // 64x392 half = 50176
constexpr int OFF_QC  = 226304;           // 196 ints
constexpr int OFF_ONE = 227088;           // 512
constexpr int SMEM_BYTES = 227600;        // <= 232448 opt-in

using FragA  = wmma::fragment<wmma::matrix_a, 16, 16, 16, __half, wmma::row_major>;
using FragBR = wmma::fragment<wmma::matrix_b, 16, 16, 16, __half, wmma::row_major>;
using FragBC = wmma::fragment<wmma::matrix_b, 16, 16, 16, __half, wmma::col_major>;
using FragC  = wmma::fragment<wmma::accumulator, 16, 16, 16, float>;
using FragCH = wmma::fragment<wmma::accumulator, 16, 16, 16, __half>;

constexpr int NF_KV = 25 * 48;
constexpr int NF_Q  = 13 * 24;
constexpr int NF_P  = 25 * 12;
}

__device__ uint4 g_wkv_f[NF_KV * 32];
__device__ uint4 g_wq_f [NF_Q  * 32];
__device__ uint4 g_wp_f [NF_P  * 32];
__device__ float g_bias_f[NH_ * 49 * NKEY];

__device__ __forceinline__ void expand_b(FragBR& f, uint4 v) {
    unsigned int w[4] = {v.x, v.y, v.z, v.w};
#pragma unroll
    for (int i = 0; i < 4; ++i) {
        const __half2 h2 = *reinterpret_cast<const __half2*>(&w[i]);
        f.x[2 * i]     = __low2half(h2);
        f.x[2 * i + 1] = __high2half(h2);
    }
}

__device__ __forceinline__ void cvt_store_half(__half* dst, int ld, const FragC& c) {
    FragCH h;
#pragma unroll
    for (int i = 0; i < 8; ++i) h.x[i] = __float2half_rn(c.x[i]);
    wmma::store_matrix_sync(dst, h, ld, wmma::mem_row_major);
}

__device__ __forceinline__ void cvt_acc_to_a(FragA& a, const FragC& c) {
#pragma unroll
    for (int i = 0; i < 8; ++i) a.x[i] = __float2half_rn(c.x[i]);
}

// out projection for MT m-tiles of one chunk; warp handles n-tile `nt`
template <int MT>
__device__ __forceinline__ void out_proj_block(
    const __half* s_qpb, float* dst, int dst_ld,
    const FragA& ones, int nt, int lane)
{
    FragC c[MT];
#pragma unroll
    for (int m = 0; m < MT; ++m) wmma::fill_fragment(c[m], 0.0f);
    uint4 nb = g_wp_f[nt * 32 + lane];
    for (int ks = 0; ks < 24; ++ks) {
        FragBR bw;
        expand_b(bw, nb);
        nb = g_wp_f[((ks + 1) * 12 + nt) * 32 + lane];
#pragma unroll
        for (int m = 0; m < MT; ++m) {
            FragA a;
            wmma::load_matrix_sync(a, s_qpb + m * 16 * SQP + ks * 16, SQP);
            wmma::mma_sync(c[m], a, bw, c[m]);
        }
    }
    {
        FragBR bw;
        expand_b(bw, nb);
#pragma unroll
        for (int m = 0; m < MT; ++m) wmma::mma_sync(c[m], ones, bw, c[m]);
    }
#pragma unroll
    for (int m = 0; m < MT; ++m)
        wmma::store_matrix_sync(dst + m * 16 * dst_ld + nt * 16, c[m], dst_ld,
                                wmma::mem_row_major);
}

// ---------------- setup kernels ----------------
__global__ void pack_frags(const float* __restrict__ w_kv, const float* __restrict__ b_kv,
                           const float* __restrict__ w_q,  const float* __restrict__ b_q,
                           const float* __restrict__ w_proj, const float* __restrict__ b_proj) {
    __shared__ __half tiles[8][256];
    const int w    = blockIdx.x * 8 + (threadIdx.x >> 5);
    const int lane = threadIdx.x & 31;
    __half* tile = tiles[threadIdx.x >> 5];
    uint4* dst;
    if (w < NF_KV) {
        const int ks = w / 48, nt = w - ks * 48, n0 = nt * 16;
        for (int e = lane; e < 256; e += 32) {
            const int r = e >> 4, c = e & 15;
            float v;
            if (ks < 24) v = w_kv[(ks * 16 + r) * 768 + n0 + c];
            else         v = (r == 0) ? b_kv[n0 + c] : 0.0f;
            tile[e] = __float2half_rn(v);
        }
        dst = g_wkv_f + w * 32;
    } else if (w < NF_KV + NF_Q) {
        const int w2 = w - NF_KV, ks = w2 / 24, nt = w2 - ks * 24, n0 = nt * 16;
        for (int e = lane; e < 256; e += 32) {
            const int r = e >> 4, c = e & 15;
            float v;
            if (ks < 12) v = w_q[(ks * 16 + r) * DIM_ + n0 + c] * SCALE_;
            else         v = (r == 0) ? b_q[n0 + c] * SCALE_ : 0.0f;
            tile[e] = __float2half_rn(v);
        }
        dst = g_wq_f + w2 * 32;
    } else if (w < NF_KV + NF_Q + NF_P) {
        const int w3 = w - NF_KV - NF_Q, ks = w3 / 12, nt = w3 - ks * 12, n0 = nt * 16;
        for (int e = lane; e < 256; e += 32) {
            const int r = e >> 4, c = e & 15;
            float v;
            if (ks < 24) v = w_proj[(ks * 16 + r) * CQ_ + n0 + c];
            else         v = (r == 0) ? b_proj[n0 + c] : 0.0f;
            tile[e] = __float2half_rn(v);
        }
        dst = g_wp_f + w3 * 32;
    } else return;
    __syncwarp();
    FragBR f;
    wmma::load_matrix_sync(f, tile, 16);
    unsigned int w4[4];
#pragma unroll
    for (int i = 0; i < 4; ++i) {
        __half2 h2 = __halves2half2(f.x[2 * i], f.x[2 * i + 1]);
        w4[i] = *reinterpret_cast<unsigned int*>(&h2);
    }
    dst[lane] = make_uint4(w4[0], w4[1], w4[2], w4[3]);
}

__global__ void pack_bias(const float* __restrict__ bias_table) {
    const int idx = blockIdx.x * blockDim.x + threadIdx.x;
    if (idx >= NH_ * 49 * NKEY) return;
    const int h   = idx / (49 * NKEY);
    const int rem = idx - h * 49 * NKEY;
    const int qc  = rem / NKEY;
    const int key = rem - qc * NKEY;
    const int qi2 = qc / 7, qj2 = qc - qi2 * 7;
    const int kp  = key * 4;
    const int ki  = kp / 14, kj = kp - ki * 14;
    const int dh  = qi2 - (ki >> 1) + 6;
    const int dw  = qj2 - (kj >> 1) + 6;
    g_bias_f[idx] = bias_table[(dh * 13 + dw) * NH_ + h];
}

// ---------------- main kernel ----------------
__global__ __launch_bounds__(NT, 1)
void wca_kernel(const float* __restrict__ kv, const float* __restrict__ q,
                float* __restrict__ out)
{
    extern __shared__ char smb[];
    __half* s_k   = (__half*)(smb + OFF_K);
    __half* s_v   = (__half*)(smb + OFF_V);
    __half* s_qin = (__half*)(smb + OFF_SCR);   // 64x200 half
    float*  s_ost = (float*)(smb + OFF_SCR);    // final partial chunk: 16x192 f32
    __half* s_qp0 = (__half*)(smb + OFF_QP0);   // O buffer A (phase1: s_x overlays)
    __half* s_qp1 = (__half*)(smb + OFF_QP1);   // O buffer B
    __half* s_x   = (__half*)(smb + OFF_QP0);
    int*    s_qc  = (int*)(smb + OFF_QC);
    __half* s_one = (__half*)(smb + OFF_ONE);

    const int b    = blockIdx.x;
    const int tid  = threadIdx.x;
    const int wid  = tid >> 5;
    const int lane = tid & 31;

    // ---- phase 0: X load + pad, ones tile, bias cells, chunk-0 q-load ----
    {
        const float4* src = (const float4*)(kv + (size_t)b * NKEY * DIM_);
        for (int i = tid; i < NKEY * 96; i += NT) {
            const int r = i / 96, c4 = (i - r * 96) * 4;
            const float4 v = src[i];
            __half* d = s_x + r * SQP + c4;
            d[0] = __float2half_rn(v.x); d[1] = __float2half_rn(v.y);
            d[2] = __float2half_rn(v.z); d[3] = __float2half_rn(v.w);
        }
        for (int i = tid; i < (NKP - NKEY) * SQP; i += NT)
            s_x[NKEY * SQP + i] = __float2half_rn(0.0f);
        if (tid < 256) s_one[tid] = __float2half_rn((tid & 15) == 0 ? 1.0f : 0.0f);
        if (tid < QN_) {
            const int qi = tid / 14, qj = tid - qi * 14;
            s_qc[tid] = (qi >> 1) * 7 + (qj >> 1);
        }
        // chunk-0 q rows (full 64)
        const float4* qsrc = (const float4*)(q + (size_t)b * QN_ * CQ_);
        for (int i = tid; i < CHUNK * 48; i += NT) {
            const int r = i / 48, c4 = (i - r * 48) * 4;
            const float4 v = qsrc[i];
            __half* d = s_qin + r * SQIN + c4;
            d[0] = __float2half_rn(v.x); d[1] = __float2half_rn(v.y);
            d[2] = __float2half_rn(v.z); d[3] = __float2half_rn(v.w);
        }
    }
    __syncthreads();

    FragA ones;
    wmma::load_matrix_sync(ones, s_one, 16);

    // ---- phase 1: kv projection, B-stationary over 4 m-tiles ----
    {
        for (int j = 0; j < 2; ++j) {
            const int nt0 = (wid * 2 + j) * 2;
            FragC c[4][2];
#pragma unroll
            for (int m = 0; m < 4; ++m) {
                wmma::fill_fragment(c[m][0], 0.0f);
                wmma::fill_fragment(c[m][1], 0.0f);
            }
            uint4 nb0 = g_wkv_f[nt0 * 32 + lane];
            uint4 nb1 = g_wkv_f[(nt0 + 1) * 32 + lane];
            for (int ks = 0; ks < 24; ++ks) {
                FragBR b0, b1;
                expand_b(b0, nb0);
                expand_b(b1, nb1);
                nb0 = g_wkv_f[((ks + 1) * 48 + nt0) * 32 + lane];
                nb1 = g_wkv_f[((ks + 1) * 48 + nt0 + 1) * 32 + lane];
#pragma unroll
                for (int m = 0; m < 4; ++m) {
                    FragA a;
                    wmma::load_matrix_sync(a, s_x + m * 16 * SQP + ks * 16, SQP);
                    wmma::mma_sync(c[m][0], a, b0, c[m][0]);
                    wmma::mma_sync(c[m][1], a, b1, c[m][1]);
                }
            }
            {
                FragBR b0, b1;
                expand_b(b0, nb0);
                expand_b(b1, nb1);
#pragma unroll
                for (int m = 0; m < 4; ++m) {
                    wmma::mma_sync(c[m][0], ones, b0, c[m][0]);
                    wmma::mma_sync(c[m][1], ones, b1, c[m][1]);
                }
            }
#pragma unroll
            for (int t = 0; t < 2; ++t) {
                const int colg = (nt0 + t) * 16;
                __half* dst = (colg < DIM_) ? (s_k + colg) : (s_v + colg - DIM_);
#pragma unroll
                for (int m = 0; m < 4; ++m)
                    cvt_store_half(dst + m * 16 * SKVH, SKVH, c[m][t]);
            }
        }
    }
    __syncthreads();   // K/V ready; qin(0) ready

    const size_t ob_base = (size_t)b * QN_ * CQ_;

    // ---- phase 2: pipelined chunks: q-proj(i) | out-proj(i-1) | attention(i) ----
    for (int i = 0; i < NCH; ++i) {
        const int q0 = i * CHUNK;
        const int nr = min(CHUNK, QN_ - q0);
        const int mt = (nr + 15) >> 4;
        __half* qpw = (i & 1) ? s_qp1 : s_qp0;

        const int h = wid;
        const int base = h * HD_;
        const int nt0 = h * 2;
        const int r0l = lane >> 2;
        const int c0l = (lane & 3) * 2;

        // q projection -> qa (register A fragments)
        FragA qa[MTMAX][2];
        {
            FragC qc[MTMAX][2];
#pragma unroll
            for (int m = 0; m < MTMAX; ++m) if (m < mt) {
                wmma::fill_fragment(qc[m][0], 0.0f);
                wmma::fill_fragment(qc[m][1], 0.0f);
            }
            uint4 nb0 = g_wq_f[nt0 * 32 + lane];
            uint4 nb1 = g_wq_f[(nt0 + 1) * 32 + lane];
            for (int ks = 0; ks < 12; ++ks) {
                FragBR b0, b1;
                expand_b(b0, nb0);
                expand_b(b1, nb1);
                nb0 = g_wq_f[((ks + 1) * 24 + nt0) * 32 + lane];
                nb1 = g_wq_f[((ks + 1) * 24 + nt0 + 1) * 32 + lane];
#pragma unroll
                for (int m = 0; m < MTMAX; ++m) if (m < mt) {
                    FragA a;
                    wmma::load_matrix_sync(a, s_qin + m * 16 * SQIN + ks * 16, SQIN);
                    wmma::mma_sync(qc[m][0], a, b0, qc[m][0]);
                    wmma::mma_sync(qc[m][1], a, b1, qc[m][1]);
                }
            }
            {
                FragBR b0, b1;
                expand_b(b0, nb0);
                expand_b(b1, nb1);
#pragma unroll
                for (int m = 0; m < MTMAX; ++m) if (m < mt) {
                    wmma::mma_sync(qc[m][0], ones, b0, qc[m][0]);
                    wmma::mma_sync(qc[m][1], ones, b1, qc[m][1]);
                }
            }
#pragma unroll
            for (int m = 0; m < MTMAX; ++m) if (m < mt) {
                cvt_acc_to_a(qa[m][0], qc[m][0]);
                cvt_acc_to_a(qa[m][1], qc[m][1]);
            }
        }

        // out-proj of previous (full) chunk — overlaps with this chunk's latency
        if (i > 0) {
            const __half* qpr = ((i - 1) & 1) ? s_qp1 : s_qp0;
            out_proj_block<MTMAX>(qpr, out + ob_base + (size_t)(q0 - CHUNK) * CQ_,
                                  CQ_, ones, wid, lane);
        }

        // attention: register-resident S/softmax/P
#pragma unroll
        for (int s = 0; s < MTMAX; ++s) if (s < mt) {
            FragC sf[4];
#pragma unroll
            for (int t = 0; t < 4; ++t) wmma::fill_fragment(sf[t], 0.0f);
#pragma unroll
            for (int ks = 0; ks < 2; ++ks) {
#pragma unroll
                for (int t = 0; t < 4; ++t) {
                    FragBC bk;
                    wmma::load_matrix_sync(bk, s_k + (t * 16) * SKVH + base + ks * 16, SKVH);
                    wmma::mma_sync(sf[t], qa[s][ks], bk, sf[t]);
                }
            }

            const float* bias0 =
                g_bias_f + (h * 49 + s_qc[min(q0 + s * 16 + r0l, QN_ - 1)]) * NKEY;
            const float* bias1 =
                g_bias_f + (h * 49 + s_qc[min(q0 + s * 16 + r0l + 8, QN_ - 1)]) * NKEY;
            float mx0 = -1e30f, mx1 = -1e30f;
#pragma unroll
            for (int t = 0; t < 4; ++t) {
                const int cb = t * 16 + c0l;
                float v;
                v = (cb     < NKEY) ? sf[t].x[0] + bias0[cb]     : -1e30f; sf[t].x[0] = v; mx0 = fmaxf(mx0, v);
                v = (cb + 1 < NKEY) ? sf[t].x[1] + bias0[cb + 1] : -1e30f; sf[t].x[1] = v; mx0 = fmaxf(mx0, v);
                v = (cb + 8 < NKEY) ? sf[t].x[4] + bias0[cb + 8] : -1e30f; sf[t].x[4] = v; mx0 = fmaxf(mx0, v);
                v = (cb + 9 < NKEY) ? sf[t].x[5] + bias0[cb + 9] : -1e30f; sf[t].x[5] = v; mx0 = fmaxf(mx0, v);
                v = (cb     < NKEY) ? sf[t].x[2] + bias1[cb]     : -1e30f; sf[t].x[2] = v; mx1 = fmaxf(mx1, v);
                v = (cb + 1 < NKEY) ? sf[t].x[3] + bias1[cb + 1] : -1e30f; sf[t].x[3] = v; mx1 = fmaxf(mx1, v);
                v = (cb + 8 < NKEY) ? sf[t].x[6] + bias1[cb + 8] : -1e30f; sf[t].x[6] = v; mx1 = fmaxf(mx1, v);
                v = (cb + 9 < NKEY) ? sf[t].x[7] + bias1[cb + 9] : -1e30f; sf[t].x[7] = v; mx1 = fmaxf(mx1, v);
            }
            mx0 = fmaxf(mx0, __shfl_xor_sync(0xffffffffu, mx0, 1));
            mx0 = fmaxf(mx0, __shfl_xor_sync(0xffffffffu, mx0, 2));
            mx1 = fmaxf(mx1, __shfl_xor_sync(0xffffffffu, mx1, 1));
            mx1 = fmaxf(mx1, __shfl_xor_sync(0xffffffffu, mx1, 2));

            float s0 = 0.f, s1 = 0.f;
#pragma unroll
            for (int t = 0; t < 4; ++t) {
                const int cb = t * 16 + c0l;
                float p;
                p = (cb     < NKEY) ? __expf(sf[t].x[0] - mx0) : 0.f; sf[t].x[0] = p; s0 += p;
                p = (cb + 1 < NKEY) ? __expf(sf[t].x[1] - mx0) : 0.f; sf[t].x[1] = p; s0 += p;
                p = (cb + 8 < NKEY) ? __expf(sf[t].x[4] - mx0) : 0.f; sf[t].x[4] = p; s0 += p;
                p = (cb + 9 < NKEY) ? __expf(sf[t].x[5] - mx0) : 0.f; sf[t].x[5] = p; s0 += p;
                p = (cb     < NKEY) ? __expf(sf[t].x[2] - mx1) : 0.f; sf[t].x[2] = p; s1 += p;
                p = (cb + 1 < NKEY) ? __expf(sf[t].x[3] - mx1) : 0.f; sf[t].x[3] = p; s1 += p;
                p = (cb + 8 < NKEY) ? __expf(sf[t].x[6] - mx1) : 0.f; sf[t].x[6] = p; s1 += p;
                p = (cb + 9 < NKEY) ? __expf(sf[t].x[7] - mx1) : 0.f; sf[t].x[7] = p; s1 += p;
            }
            s0 += __shfl_xor_sync(0xffffffffu, s0, 1);
            s0 += __shfl_xor_sync(0xffffffffu, s0, 2);
            s1 += __shfl_xor_sync(0xffffffffu, s1, 1);
            s1 += __shfl_xor_sync(0xffffffffu, s1, 2);
            const float inv0 = 1.0f / s0;
            const float inv1 = 1.0f / s1;

            FragA pf[4];
#pragma unroll
            for (int t = 0; t < 4; ++t) {
                pf[t].x[0] = __float2half_rn(sf[t].x[0] * inv0);
                pf[t].x[1] = __float2half_rn(sf[t].x[1] * inv0);
                pf[t].x[4] = __float2half_rn(sf[t].x[4] * inv0);
                pf[t].x[5] = __float2half_rn(sf[t].x[5] * inv0);
                pf[t].x[2] = __float2half_rn(sf[t].x[2] * inv1);
                pf[t].x[3] = __float2half_rn(sf[t].x[3] * inv1);
                pf[t].x[6] = __float2half_rn(sf[t].x[6] * inv1);
                pf[t].x[7] = __float2half_rn(sf[t].x[7] * inv1);
            }

            FragC o[2];
            wmma::fill_fragment(o[0], 0.0f);
            wmma::fill_fragment(o[1], 0.0f);
#pragma unroll
            for (int ks = 0; ks < 4; ++ks) {
#pragma unroll
                for (int t = 0; t < 2; ++t) {
                    FragBR bv;
                    wmma::load_matrix_sync(bv, s_v + ks * 16 * SKVH + base + t * 16, SKVH);
                    wmma::mma_sync(o[t], pf[ks], bv, o[t]);
                }
            }
#pragma unroll
            for (int t = 0; t < 2; ++t)
                cvt_store_half(qpw + s * 16 * SQP + base + t * 16, SQP, o[t]);
        }
        __syncthreads();   // O(i) complete; q-proj(i) done -> qin reusable

        if (i + 1 < NCH) {
            const int q0n = (i + 1) * CHUNK;
            const int nrn = min(CHUNK, QN_ - q0n);
            const int mtn = (nrn + 15) >> 4;
            const float4* src = (const float4*)(q + ob_base + (size_t)q0n * CQ_);
            for (int e = tid; e < mtn * 16 * 48; e += NT) {
                const int r = e / 48, c4 = (e - r * 48) * 4;
                float4 v = make_float4(0.f, 0.f, 0.f, 0.f);
                if (r < nrn) v = src[e];
                __half* d = s_qin + r * SQIN + c4;
                d[0] = __float2half_rn(v.x); d[1] = __float2half_rn(v.y);
                d[2] = __float2half_rn(v.z); d[3] = __float2half_rn(v.w);
            }
            __syncthreads();
        }
    }

    // ---- final out-proj (last chunk, partial: nr=4, mt=1) ----
    {
        const __half* qpr = ((NCH - 1) & 1) ? s_qp1 : s_qp0;
        out_proj_block<1>(qpr, s_ost, CQ_, ones, wid, lane);
        __syncthreads();
        const int q0l = (NCH - 1) * CHUNK;
        const int nrl = QN_ - q0l;               // 4
        float4* ob = (float4*)(out + ob_base + (size_t)q0l * CQ_);
        for (int e = tid; e < nrl * 48; e += NT) ob[e] = ((float4*)s_ost)[e];
    }
}

extern "C" void kernel_launch(void* const* d_in, const int* in_sizes, int n_in,
                              void* d_out, int out_size) {
    const float* kv         = (const float*)d_in[0];
    const float* q          = (const float*)d_in[1];
    const float* w_kv       = (const float*)d_in[2];
    const float* b_kv       = (const float*)d_in[3];
    const float* w_q        = (const float*)d_in[4];
    const float* b_q        = (const float*)d_in[5];
    const float* bias_table = (const float*)d_in[6];
    const float* w_proj     = (const float*)d_in[7];
    const float* b_proj     = (const float*)d_in[8];
    float* out = (float*)d_out;

    const int B = in_sizes[0] / (NKEY * DIM_);              // 2048
    const int nfrag = NF_KV + NF_Q + NF_P;                  // 1812
    pack_frags<<<(nfrag + 7) / 8, 256>>>(w_kv, b_kv, w_q, b_q, w_proj, b_proj);
    pack_bias<<<(NH_ * 49 * NKEY + 511) / 512, 512>>>(bias_table);

    cudaFuncSetAttribute(wca_kernel, cudaFuncAttributeMaxDynamicSharedMemorySize, SMEM_BYTES);
    wca_kernel<<<B, NT, SMEM_BYTES>>>(kv, q, out);
}

// round 13
// speedup vs baseline: 1.3141x; 1.0373x over previous
#include <cuda_runtime.h>
#include <cuda_fp16.h>
#include <mma.h>
#include <cstdint>

using namespace nvcuda;

namespace {
constexpr int NKEY = 49;
constexpr int QN_  = 196;
constexpr int DIM_ = 384;
constexpr int NH_  = 12;
constexpr int HD_  = 32;
constexpr int CQ_  = 192;
constexpr float SCALE_ = 0.17677669529663687f;

constexpr int NT    = 384;   // 12 warps
constexpr int NW    = 12;
constexpr int CHUNK = 64;
constexpr int NKP   = 64;

constexpr int SKVH = 392;    // K/V row stride (halves)
constexpr int SQP  = 392;    // qp / x row stride (halves)
constexpr int SQIN = 200;    // q-input row stride (halves)

// smem byte offsets
constexpr int OFF_K   = 0;                // 64*392*2 = 50176
constexpr int OFF_V   = 50176;
constexpr int OFF_SCR = 100352;           // qin 64x200 half / ost 16x192 f32
constexpr int OFF_QP0 = 125952;           // 64x392 half (phase1: s_x overlays)
constexpr int OFF_QP1 = 176128;           // 64x392 half
constexpr int OFF_QC  = 226304;           // 196 ints
constexpr int OFF_ONE = 227088;
constexpr int SMEM_BYTES = 227600;

using FragA  = wmma::fragment<wmma::matrix_a, 16, 16, 16, __half, wmma::row_major>;
using FragBR = wmma::fragment<wmma::matrix_b, 16, 16, 16, __half, wmma::row_major>;
using FragBC = wmma::fragment<wmma::matrix_b, 16, 16, 16, __half, wmma::col_major>;
using FragC  = wmma::fragment<wmma::accumulator, 16, 16, 16, float>;
using FragCH = wmma::fragment<wmma::accumulator, 16, 16, 16, __half>;

constexpr int NF_KV = 25 * 48;
constexpr int NF_Q  = 13 * 24;
constexpr int NF_P  = 25 * 12;
constexpr int NFRAG = NF_KV + NF_Q + NF_P;        // 1812
constexpr int FRAG_BLOCKS = (NFRAG + 7) / 8;      // 227
constexpr int BIAS_ELEMS  = NH_ * 49 * NKEY;      // 28812
constexpr int BIAS_BLOCKS = (BIAS_ELEMS + 255) / 256;  // 113
}

__device__ uint4 g_wkv_f[NF_KV * 32];
__device__ uint4 g_wq_f [NF_Q  * 32];
__device__ uint4 g_wp_f [NF_P  * 32];
__device__ float g_bias_f[BIAS_ELEMS];

__device__ __forceinline__ void expand_b(FragBR& f, uint4 v) {
    unsigned int w[4] = {v.x, v.y, v.z, v.w};
#pragma unroll
    for (int i = 0; i < 4; ++i) {
        const __half2 h2 = *reinterpret_cast<const __half2*>(&w[i]);
        f.x[2 * i]     = __low2half(h2);
        f.x[2 * i + 1] = __high2half(h2);
    }
}

__device__ __forceinline__ void cvt_store_half(__half* dst, int ld, const FragC& c) {
    FragCH h;
#pragma unroll
    for (int i = 0; i < 8; ++i) h.x[i] = __float2half_rn(c.x[i]);
    wmma::store_matrix_sync(dst, h, ld, wmma::mem_row_major);
}

__device__ __forceinline__ void cvt_acc_to_a(FragA& a, const FragC& c) {
#pragma unroll
    for (int i = 0; i < 8; ++i) a.x[i] = __float2half_rn(c.x[i]);
}

// ---- q projection for MT m-tiles of head h; results as register A-fragments ----
template <int MT>
__device__ __forceinline__ void qproj(const __half* s_qin, FragA (&qa)[MT][2],
                                      const FragA& ones, int h, int lane)
{
    const int nt0 = h * 2;
    FragC qc[MT][2];
#pragma unroll
    for (int m = 0; m < MT; ++m) {
        wmma::fill_fragment(qc[m][0], 0.0f);
        wmma::fill_fragment(qc[m][1], 0.0f);
    }
    uint4 nb0 = g_wq_f[nt0 * 32 + lane];
    uint4 nb1 = g_wq_f[(nt0 + 1) * 32 + lane];
    for (int ks = 0; ks < 12; ++ks) {
        FragBR b0, b1;
        expand_b(b0, nb0);
        expand_b(b1, nb1);
        nb0 = g_wq_f[((ks + 1) * 24 + nt0) * 32 + lane];
        nb1 = g_wq_f[((ks + 1) * 24 + nt0 + 1) * 32 + lane];
#pragma unroll
        for (int m = 0; m < MT; ++m) {
            FragA a;
            wmma::load_matrix_sync(a, s_qin + m * 16 * SQIN + ks * 16, SQIN);
            wmma::mma_sync(qc[m][0], a, b0, qc[m][0]);
            wmma::mma_sync(qc[m][1], a, b1, qc[m][1]);
        }
    }
    {
        FragBR b0, b1;
        expand_b(b0, nb0);
        expand_b(b1, nb1);
#pragma unroll
        for (int m = 0; m < MT; ++m) {
            wmma::mma_sync(qc[m][0], ones, b0, qc[m][0]);
            wmma::mma_sync(qc[m][1], ones, b1, qc[m][1]);
        }
    }
#pragma unroll
    for (int m = 0; m < MT; ++m) {
        cvt_acc_to_a(qa[m][0], qc[m][0]);
        cvt_acc_to_a(qa[m][1], qc[m][1]);
    }
}

// ---- attention for MT sub-chunks of head h; O -> qpw as half ----
template <int MT, bool CLAMP>
__device__ __forceinline__ void attn(const FragA (&qa)[MT][2],
                                     const __half* s_k, const __half* s_v,
                                     __half* qpw, const int* s_qc,
                                     int q0, int h, int lane)
{
    const int base = h * HD_;
    const int r0l = lane >> 2;
    const int c0l = (lane & 3) * 2;
#pragma unroll
    for (int s = 0; s < MT; ++s) {
        FragC sf[4];
#pragma unroll
        for (int t = 0; t < 4; ++t) wmma::fill_fragment(sf[t], 0.0f);
#pragma unroll
        for (int ks = 0; ks < 2; ++ks) {
#pragma unroll
            for (int t = 0; t < 4; ++t) {
                FragBC bk;
                wmma::load_matrix_sync(bk, s_k + (t * 16) * SKVH + base + ks * 16, SKVH);
                wmma::mma_sync(sf[t], qa[s][ks], bk, sf[t]);
            }
        }

        int i0 = q0 + s * 16 + r0l;
        int i1 = i0 + 8;
        if (CLAMP) { i0 = min(i0, QN_ - 1); i1 = min(i1, QN_ - 1); }
        const float* bias0 = g_bias_f + (h * 49 + s_qc[i0]) * NKEY;
        const float* bias1 = g_bias_f + (h * 49 + s_qc[i1]) * NKEY;
        float mx0 = -1e30f, mx1 = -1e30f;
#pragma unroll
        for (int t = 0; t < 4; ++t) {
            const int cb = t * 16 + c0l;
            float v;
            v = (cb     < NKEY) ? sf[t].x[0] + bias0[cb]     : -1e30f; sf[t].x[0] = v; mx0 = fmaxf(mx0, v);
            v = (cb + 1 < NKEY) ? sf[t].x[1] + bias0[cb + 1] : -1e30f; sf[t].x[1] = v; mx0 = fmaxf(mx0, v);
            v = (cb + 8 < NKEY) ? sf[t].x[4] + bias0[cb + 8] : -1e30f; sf[t].x[4] = v; mx0 = fmaxf(mx0, v);
            v = (cb + 9 < NKEY) ? sf[t].x[5] + bias0[cb + 9] : -1e30f; sf[t].x[5] = v; mx0 = fmaxf(mx0, v);
            v = (cb     < NKEY) ? sf[t].x[2] + bias1[cb]     : -1e30f; sf[t].x[2] = v; mx1 = fmaxf(mx1, v);
            v = (cb + 1 < NKEY) ? sf[t].x[3] + bias1[cb + 1] : -1e30f; sf[t].x[3] = v; mx1 = fmaxf(mx1, v);
            v = (cb + 8 < NKEY) ? sf[t].x[6] + bias1[cb + 8] : -1e30f; sf[t].x[6] = v; mx1 = fmaxf(mx1, v);
            v = (cb + 9 < NKEY) ? sf[t].x[7] + bias1[cb + 9] : -1e30f; sf[t].x[7] = v; mx1 = fmaxf(mx1, v);
        }
        mx0 = fmaxf(mx0, __shfl_xor_sync(0xffffffffu, mx0, 1));
        mx0 = fmaxf(mx0, __shfl_xor_sync(0xffffffffu, mx0, 2));
        mx1 = fmaxf(mx1, __shfl_xor_sync(0xffffffffu, mx1, 1));
        mx1 = fmaxf(mx1, __shfl_xor_sync(0xffffffffu, mx1, 2));

        float s0 = 0.f, s1 = 0.f;
#pragma unroll
        for (int t = 0; t < 4; ++t) {
            const int cb = t * 16 + c0l;
            float p;
            p = (cb     < NKEY) ? __expf(sf[t].x[0] - mx0) : 0.f; sf[t].x[0] = p; s0 += p;
            p = (cb + 1 < NKEY) ? __expf(sf[t].x[1] - mx0) : 0.f; sf[t].x[1] = p; s0 += p;
            p = (cb + 8 < NKEY) ? __expf(sf[t].x[4] - mx0) : 0.f; sf[t].x[4] = p; s0 += p;
            p = (cb + 9 < NKEY) ? __expf(sf[t].x[5] - mx0) : 0.f; sf[t].x[5] = p; s0 += p;
            p = (cb     < NKEY) ? __expf(sf[t].x[2] - mx1) : 0.f; sf[t].x[2] = p; s1 += p;
            p = (cb + 1 < NKEY) ? __expf(sf[t].x[3] - mx1) : 0.f; sf[t].x[3] = p; s1 += p;
            p = (cb + 8 < NKEY) ? __expf(sf[t].x[6] - mx1) : 0.f; sf[t].x[6] = p; s1 += p;
            p = (cb + 9 < NKEY) ? __expf(sf[t].x[7] - mx1) : 0.f; sf[t].x[7] = p; s1 += p;
        }
        s0 += __shfl_xor_sync(0xffffffffu, s0, 1);
        s0 += __shfl_xor_sync(0xffffffffu, s0, 2);
        s1 += __shfl_xor_sync(0xffffffffu, s1, 1);
        s1 += __shfl_xor_sync(0xffffffffu, s1, 2);
        const float inv0 = 1.0f / s0;
        const float inv1 = 1.0f / s1;

        FragA pf[4];
#pragma unroll
        for (int t = 0; t < 4; ++t) {
            pf[t].x[0] = __float2half_rn(sf[t].x[0] * inv0);
            pf[t].x[1] = __float2half_rn(sf[t].x[1] * inv0);
            pf[t].x[4] = __float2half_rn(sf[t].x[4] * inv0);
            pf[t].x[5] = __float2half_rn(sf[t].x[5] * inv0);
            pf[t].x[2] = __float2half_rn(sf[t].x[2] * inv1);
            pf[t].x[3] = __float2half_rn(sf[t].x[3] * inv1);
            pf[t].x[6] = __float2half_rn(sf[t].x[6] * inv1);
            pf[t].x[7] = __float2half_rn(sf[t].x[7] * inv1);
        }

        // PV with split accumulators (4 independent HMMA chains)
        FragC o[2], o2[2];
        wmma::fill_fragment(o[0], 0.0f);
        wmma::fill_fragment(o[1], 0.0f);
        wmma::fill_fragment(o2[0], 0.0f);
        wmma::fill_fragment(o2[1], 0.0f);
#pragma unroll
        for (int ks = 0; ks < 2; ++ks) {
#pragma unroll
            for (int t = 0; t < 2; ++t) {
                FragBR bv;
                wmma::load_matrix_sync(bv, s_v + ks * 16 * SKVH + base + t * 16, SKVH);
                wmma::mma_sync(o[t], pf[ks], bv, o[t]);
            }
        }
#pragma unroll
        for (int ks = 2; ks < 4; ++ks) {
#pragma unroll
            for (int t = 0; t < 2; ++t) {
                FragBR bv;
                wmma::load_matrix_sync(bv, s_v + ks * 16 * SKVH + base + t * 16, SKVH);
                wmma::mma_sync(o2[t], pf[ks], bv, o2[t]);
            }
        }
#pragma unroll
        for (int t = 0; t < 2; ++t) {
#pragma unroll
            for (int e = 0; e < 8; ++e) o[t].x[e] += o2[t].x[e];
            cvt_store_half(qpw + s * 16 * SQP + base + t * 16, SQP, o[t]);
        }
    }
}

// ---- out projection for MT m-tiles; warp handles n-tile nt ----
template <int MT>
__device__ __forceinline__ void out_proj_block(
    const __half* s_qpb, float* dst, int dst_ld,
    const FragA& ones, int nt, int lane)
{
    FragC c[MT];
#pragma unroll
    for (int m = 0; m < MT; ++m) wmma::fill_fragment(c[m], 0.0f);
    uint4 nb = g_wp_f[nt * 32 + lane];
    for (int ks = 0; ks < 24; ++ks) {
        FragBR bw;
        expand_b(bw, nb);
        nb = g_wp_f[((ks + 1) * 12 + nt) * 32 + lane];
#pragma unroll
        for (int m = 0; m < MT; ++m) {
            FragA a;
            wmma::load_matrix_sync(a, s_qpb + m * 16 * SQP + ks * 16, SQP);
            wmma::mma_sync(c[m], a, bw, c[m]);
        }
    }
    {
        FragBR bw;
        expand_b(bw, nb);
#pragma unroll
        for (int m = 0; m < MT; ++m) wmma::mma_sync(c[m], ones, bw, c[m]);
    }
#pragma unroll
    for (int m = 0; m < MT; ++m)
        wmma::store_matrix_sync(dst + m * 16 * dst_ld + nt * 16, c[m], dst_ld,
                                wmma::mem_row_major);
}

// ---------------- single merged setup kernel ----------------
__global__ void pack_setup(const float* __restrict__ w_kv, const float* __restrict__ b_kv,
                           const float* __restrict__ w_q,  const float* __restrict__ b_q,
                           const float* __restrict__ w_proj, const float* __restrict__ b_proj,
                           const float* __restrict__ bias_table) {
    if (blockIdx.x >= FRAG_BLOCKS) {
        const int idx = (blockIdx.x - FRAG_BLOCKS) * 256 + threadIdx.x;
        if (idx >= BIAS_ELEMS) return;
        const int h   = idx / (49 * NKEY);
        const int rem = idx - h * 49 * NKEY;
        const int qc  = rem / NKEY;
        const int key = rem - qc * NKEY;
        const int qi2 = qc / 7, qj2 = qc - qi2 * 7;
        const int kp  = key * 4;
        const int ki  = kp / 14, kj = kp - ki * 14;
        const int dh  = qi2 - (ki >> 1) + 6;
        const int dw  = qj2 - (kj >> 1) + 6;
        g_bias_f[idx] = bias_table[(dh * 13 + dw) * NH_ + h];
        return;
    }
    __shared__ __half tiles[8][256];
    const int w    = blockIdx.x * 8 + (threadIdx.x >> 5);
    const int lane = threadIdx.x & 31;
    __half* tile = tiles[threadIdx.x >> 5];
    uint4* dst;
    if (w < NF_KV) {
        const int ks = w / 48, nt = w - ks * 48, n0 = nt * 16;
        for (int e = lane; e < 256; e += 32) {
            const int r = e >> 4, c = e & 15;
            float v;
            if (ks < 24) v = w_kv[(ks * 16 + r) * 768 + n0 + c];
            else         v = (r == 0) ? b_kv[n0 + c] : 0.0f;
            tile[e] = __float2half_rn(v);
        }
        dst = g_wkv_f + w * 32;
    } else if (w < NF_KV + NF_Q) {
        const int w2 = w - NF_KV, ks = w2 / 24, nt = w2 - ks * 24, n0 = nt * 16;
        for (int e = lane; e < 256; e += 32) {
            const int r = e >> 4, c = e & 15;
            float v;
            if (ks < 12) v = w_q[(ks * 16 + r) * DIM_ + n0 + c] * SCALE_;
            else         v = (r == 0) ? b_q[n0 + c] * SCALE_ : 0.0f;
            tile[e] = __float2half_rn(v);
        }
        dst = g_wq_f + w2 * 32;
    } else if (w < NFRAG) {
        const int w3 = w - NF_KV - NF_Q, ks = w3 / 12, nt = w3 - ks * 12, n0 = nt * 16;
        for (int e = lane; e < 256; e += 32) {
            const int r = e >> 4, c = e & 15;
            float v;
            if (ks < 24) v = w_proj[(ks * 16 + r) * CQ_ + n0 + c];
            else         v = (r == 0) ? b_proj[n0 + c] : 0.0f;
            tile[e] = __float2half_rn(v);
        }
        dst = g_wp_f + w3 * 32;
    } else return;
    __syncwarp();
    FragBR f;
    wmma::load_matrix_sync(f, tile, 16);
    unsigned int w4[4];
#pragma unroll
    for (int i = 0; i < 4; ++i) {
        __half2 h2 = __halves2half2(f.x[2 * i], f.x[2 * i + 1]);
        w4[i] = *reinterpret_cast<unsigned int*>(&h2);
    }
    dst[lane] = make_uint4(w4[0], w4[1], w4[2], w4[3]);
}

// ---------------- main kernel ----------------
__global__ __launch_bounds__(NT, 1)
void wca_kernel(const float* __restrict__ kv, const float* __restrict__ q,
                float* __restrict__ out)
{
    extern __shared__ char smb[];
    __half* s_k   = (__half*)(smb + OFF_K);
    __half* s_v   = (__half*)(smb + OFF_V);
    __half* s_qin = (__half*)(smb + OFF_SCR);
    float*  s_ost = (float*)(smb + OFF_SCR);
    __half* s_qp0 = (__half*)(smb + OFF_QP0);
    __half* s_qp1 = (__half*)(smb + OFF_QP1);
    __half* s_x   = (__half*)(smb + OFF_QP0);
    int*    s_qc  = (int*)(smb + OFF_QC);
    __half* s_one = (__half*)(smb + OFF_ONE);

    const int b    = blockIdx.x;
    const int tid  = threadIdx.x;
    const int wid  = tid >> 5;
    const int lane = tid & 31;

    // ---- phase 0: X load + pad, ones tile, bias cells, chunk-0 q-load ----
    {
        const float4* src = (const float4*)(kv + (size_t)b * NKEY * DIM_);
        for (int i = tid; i < NKEY * 96; i += NT) {
            const int r = i / 96, c4 = (i - r * 96) * 4;
            const float4 v = src[i];
            __half* d = s_x + r * SQP + c4;
            d[0] = __float2half_rn(v.x); d[1] = __float2half_rn(v.y);
            d[2] = __float2half_rn(v.z); d[3] = __float2half_rn(v.w);
        }
        for (int i = tid; i < (NKP - NKEY) * SQP; i += NT)
            s_x[NKEY * SQP + i] = __float2half_rn(0.0f);
        if (tid < 256) s_one[tid] = __float2half_rn((tid & 15) == 0 ? 1.0f : 0.0f);
        if (tid < QN_) {
            const int qi = tid / 14, qj = tid - qi * 14;
            s_qc[tid] = (qi >> 1) * 7 + (qj >> 1);
        }
        const float4* qsrc = (const float4*)(q + (size_t)b * QN_ * CQ_);
        for (int i = tid; i < CHUNK * 48; i += NT) {
            const int r = i / 48, c4 = (i - r * 48) * 4;
            const float4 v = qsrc[i];
            __half* d = s_qin + r * SQIN + c4;
            d[0] = __float2half_rn(v.x); d[1] = __float2half_rn(v.y);
            d[2] = __float2half_rn(v.z); d[3] = __float2half_rn(v.w);
        }
    }
    __syncthreads();

    FragA ones;
    wmma::load_matrix_sync(ones, s_one, 16);

    // ---- phase 1: kv projection, B-stationary over 4 m-tiles ----
    {
        for (int j = 0; j < 2; ++j) {
            const int nt0 = (wid * 2 + j) * 2;
            FragC c[4][2];
#pragma unroll
            for (int m = 0; m < 4; ++m) {
                wmma::fill_fragment(c[m][0], 0.0f);
                wmma::fill_fragment(c[m][1], 0.0f);
            }
            uint4 nb0 = g_wkv_f[nt0 * 32 + lane];
            uint4 nb1 = g_wkv_f[(nt0 + 1) * 32 + lane];
            for (int ks = 0; ks < 24; ++ks) {
                FragBR b0, b1;
                expand_b(b0, nb0);
                expand_b(b1, nb1);
                nb0 = g_wkv_f[((ks + 1) * 48 + nt0) * 32 + lane];
                nb1 = g_wkv_f[((ks + 1) * 48 + nt0 + 1) * 32 + lane];
#pragma unroll
                for (int m = 0; m < 4; ++m) {
                    FragA a;
                    wmma::load_matrix_sync(a, s_x + m * 16 * SQP + ks * 16, SQP);
                    wmma::mma_sync(c[m][0], a, b0, c[m][0]);
                    wmma::mma_sync(c[m][1], a, b1, c[m][1]);
                }
            }
            {
                FragBR b0, b1;
                expand_b(b0, nb0);
                expand_b(b1, nb1);
#pragma unroll
                for (int m = 0; m < 4; ++m) {
                    wmma::mma_sync(c[m][0], ones, b0, c[m][0]);
                    wmma::mma_sync(c[m][1], ones, b1, c[m][1]);
                }
            }
#pragma unroll
            for (int t = 0; t < 2; ++t) {
                const int colg = (nt0 + t) * 16;
                __half* dst = (colg < DIM_) ? (s_k + colg) : (s_v + colg - DIM_);
#pragma unroll
                for (int m = 0; m < 4; ++m)
                    cvt_store_half(dst + m * 16 * SKVH, SKVH, c[m][t]);
            }
        }
    }
    __syncthreads();   // K/V ready; qin(0) ready

    const size_t ob_base = (size_t)b * QN_ * CQ_;

    // ---- phase 2: 3 full chunks, pipelined out-proj ----
    for (int i = 0; i < 3; ++i) {
        const int q0 = i * CHUNK;
        __half* qpw = (i & 1) ? s_qp1 : s_qp0;

        FragA qa[4][2];
        qproj<4>(s_qin, qa, ones, wid, lane);

        if (i > 0) {
            const __half* qpr = ((i - 1) & 1) ? s_qp1 : s_qp0;
            out_proj_block<4>(qpr, out + ob_base + (size_t)(q0 - CHUNK) * CQ_,
                              CQ_, ones, wid, lane);
        }

        attn<4, false>(qa, s_k, s_v, qpw, s_qc, q0, wid, lane);
        __syncthreads();   // O(i) complete; qin consumed

        // load next chunk's q rows
        {
            const int q0n = q0 + CHUNK;
            const int nrn = (i == 2) ? (QN_ - 3 * CHUNK) : CHUNK;   // 4 or 64
            const int mtn = (i == 2) ? 1 : 4;
            const float4* src = (const float4*)(q + ob_base + (size_t)q0n * CQ_);
            for (int e = tid; e < mtn * 16 * 48; e += NT) {
                const int r = e / 48, c4 = (e - r * 48) * 4;
                float4 v = make_float4(0.f, 0.f, 0.f, 0.f);
                if (r < nrn) v = src[e];
                __half* d = s_qin + r * SQIN + c4;
                d[0] = __float2half_rn(v.x); d[1] = __float2half_rn(v.y);
                d[2] = __float2half_rn(v.z); d[3] = __float2half_rn(v.w);
            }
            __syncthreads();
        }
    }

    // ---- tail chunk (rows 192..195, MT=1) ----
    {
        FragA qa1[1][2];
        qproj<1>(s_qin, qa1, ones, wid, lane);

        // out-proj of chunk 2 (buffer parity 0)
        out_proj_block<4>(s_qp0, out + ob_base + (size_t)(2 * CHUNK) * CQ_,
                          CQ_, ones, wid, lane);

        attn<1, true>(qa1, s_k, s_v, s_qp1, s_qc, 3 * CHUNK, wid, lane);
        __syncthreads();

        out_proj_block<1>(s_qp1, s_ost, CQ_, ones, wid, lane);
        __syncthreads();

        const int nrl = QN_ - 3 * CHUNK;   // 4
        float4* ob = (float4*)(out + ob_base + (size_t)(3 * CHUNK) * CQ_);
        for (int e = tid; e < nrl * 48; e += NT) ob[e] = ((float4*)s_ost)[e];
    }
}

extern "C" void kernel_launch(void* const* d_in, const int* in_sizes, int n_in,
                              void* d_out, int out_size) {
    const float* kv         = (const float*)d_in[0];
    const float* q          = (const float*)d_in[1];
    const float* w_kv       = (const float*)d_in[2];
    const float* b_kv       = (const float*)d_in[3];
    const float* w_q        = (const float*)d_in[4];
    const float* b_q        = (const float*)d_in[5];
    const float* bias_table = (const float*)d_in[6];
    const float* w_proj     = (const float*)d_in[7];
    const float* b_proj     = (const float*)d_in[8];
    float* out = (float*)d_out;

    const int B = in_sizes[0] / (NKEY * DIM_);              // 2048
    pack_setup<<<FRAG_BLOCKS + BIAS_BLOCKS, 256>>>(w_kv, b_kv, w_q, b_q,
                                                   w_proj, b_proj, bias_table);

    cudaFuncSetAttribute(wca_kernel, cudaFuncAttributeMaxDynamicSharedMemorySize, SMEM_BYTES);
    wca_kernel<<<B, NT, SMEM_BYTES>>>(kv, q, out);
}

// round 14
// speedup vs baseline: 1.3646x; 1.0384x over previous
#include <cuda_runtime.h>
#include <cuda_fp16.h>
#include <mma.h>
#include <cstdint>

using namespace nvcuda;

namespace {
constexpr int NKEY = 49;
constexpr int QN_  = 196;
constexpr int DIM_ = 384;
constexpr int NH_  = 12;
constexpr int HD_  = 32;
constexpr int CQ_  = 192;
constexpr float SCALE_ = 0.17677669529663687f;

constexpr int NT    = 384;   // 12 warps
constexpr int NW    = 12;
constexpr int CHUNK = 64;
constexpr int NKP   = 64;

constexpr int SKVH = 392;    // K/V row stride (halves)
constexpr int SQP  = 392;    // qp / x row stride (halves)
constexpr int SQIN = 200;    // q-input row stride (halves)
constexpr int BSTR = 64;     // bias row stride (floats)

// smem byte offsets
constexpr int OFF_K   = 0;                // 64*392*2 = 50176
constexpr int OFF_V   = 50176;
constexpr int OFF_SCR = 100352;           // qin 64x200 half / ost 16x192 f32
constexpr int OFF_QP0 = 125952;           // 64x392 half (phase1: s_x overlays)
constexpr int OFF_QP1 = 176128;           // 64x392 half
constexpr int OFF_QC  = 226304;           // 196 ints
constexpr int OFF_ONE = 227088;
constexpr int SMEM_BYTES = 227600;

using FragA  = wmma::fragment<wmma::matrix_a, 16, 16, 16, __half, wmma::row_major>;
using FragBR = wmma::fragment<wmma::matrix_b, 16, 16, 16, __half, wmma::row_major>;
using FragBC = wmma::fragment<wmma::matrix_b, 16, 16, 16, __half, wmma::col_major>;
using FragC  = wmma::fragment<wmma::accumulator, 16, 16, 16, float>;
using FragCH = wmma::fragment<wmma::accumulator, 16, 16, 16, __half>;

constexpr int NF_KV = 25 * 48;
constexpr int NF_Q  = 13 * 24;
constexpr int NF_P  = 25 * 12;
constexpr int NFRAG = NF_KV + NF_Q + NF_P;        // 1812
constexpr int FRAG_BLOCKS = (NFRAG + 7) / 8;      // 227
constexpr int BIAS_ELEMS  = NH_ * 49 * BSTR;      // 37632
constexpr int BIAS_BLOCKS = (BIAS_ELEMS + 255) / 256;
}

__device__ uint4 g_wkv_f[NF_KV * 32];
__device__ uint4 g_wq_f [NF_Q  * 32];
__device__ uint4 g_wp_f [NF_P  * 32];
__device__ float g_bias_f[BIAS_ELEMS];

__device__ __forceinline__ void expand_b(FragBR& f, uint4 v) {
    unsigned int w[4] = {v.x, v.y, v.z, v.w};
#pragma unroll
    for (int i = 0; i < 4; ++i) {
        const __half2 h2 = *reinterpret_cast<const __half2*>(&w[i]);
        f.x[2 * i]     = __low2half(h2);
        f.x[2 * i + 1] = __high2half(h2);
    }
}

__device__ __forceinline__ void cvt_store_half(__half* dst, int ld, const FragC& c) {
    FragCH h;
#pragma unroll
    for (int i = 0; i < 8; ++i) h.x[i] = __float2half_rn(c.x[i]);
    wmma::store_matrix_sync(dst, h, ld, wmma::mem_row_major);
}

__device__ __forceinline__ void cvt_acc_to_a(FragA& a, const FragC& c) {
#pragma unroll
    for (int i = 0; i < 8; ++i) a.x[i] = __float2half_rn(c.x[i]);
}

// ---- q projection for MT m-tiles of head h; results as register A-fragments ----
template <int MT>
__device__ __forceinline__ void qproj(const __half* s_qin, FragA (&qa)[MT][2],
                                      const FragA& ones, int h, int lane)
{
    const int nt0 = h * 2;
    FragC qc[MT][2];
#pragma unroll
    for (int m = 0; m < MT; ++m) {
        wmma::fill_fragment(qc[m][0], 0.0f);
        wmma::fill_fragment(qc[m][1], 0.0f);
    }
    uint4 nb0 = g_wq_f[nt0 * 32 + lane];
    uint4 nb1 = g_wq_f[(nt0 + 1) * 32 + lane];
    for (int ks = 0; ks < 12; ++ks) {
        FragBR b0, b1;
        expand_b(b0, nb0);
        expand_b(b1, nb1);
        nb0 = g_wq_f[((ks + 1) * 24 + nt0) * 32 + lane];
        nb1 = g_wq_f[((ks + 1) * 24 + nt0 + 1) * 32 + lane];
#pragma unroll
        for (int m = 0; m < MT; ++m) {
            FragA a;
            wmma::load_matrix_sync(a, s_qin + m * 16 * SQIN + ks * 16, SQIN);
            wmma::mma_sync(qc[m][0], a, b0, qc[m][0]);
            wmma::mma_sync(qc[m][1], a, b1, qc[m][1]);
        }
    }
    {
        FragBR b0, b1;
        expand_b(b0, nb0);
        expand_b(b1, nb1);
#pragma unroll
        for (int m = 0; m < MT; ++m) {
            wmma::mma_sync(qc[m][0], ones, b0, qc[m][0]);
            wmma::mma_sync(qc[m][1], ones, b1, qc[m][1]);
        }
    }
#pragma unroll
    for (int m = 0; m < MT; ++m) {
        cvt_acc_to_a(qa[m][0], qc[m][0]);
        cvt_acc_to_a(qa[m][1], qc[m][1]);
    }
}

// ---- softmax on one 16x64 S tile (registers) -> pre-normalized half P ----
__device__ __forceinline__ void softmax_pf(FragC (&sf)[4], FragA (&pf)[4],
                                           const float* bias0, const float* bias1,
                                           int c0l)
{
    float mx0 = -1e30f, mx1 = -1e30f;
#pragma unroll
    for (int t = 0; t < 4; ++t) {
        const int cb = t * 16 + c0l;
        const float2 b0a = *(const float2*)(bias0 + cb);
        const float2 b0b = *(const float2*)(bias0 + cb + 8);
        const float2 b1a = *(const float2*)(bias1 + cb);
        const float2 b1b = *(const float2*)(bias1 + cb + 8);
        float v;
        v = (cb     < NKEY) ? sf[t].x[0] + b0a.x : -1e30f; sf[t].x[0] = v; mx0 = fmaxf(mx0, v);
        v = (cb + 1 < NKEY) ? sf[t].x[1] + b0a.y : -1e30f; sf[t].x[1] = v; mx0 = fmaxf(mx0, v);
        v = (cb + 8 < NKEY) ? sf[t].x[4] + b0b.x : -1e30f; sf[t].x[4] = v; mx0 = fmaxf(mx0, v);
        v = (cb + 9 < NKEY) ? sf[t].x[5] + b0b.y : -1e30f; sf[t].x[5] = v; mx0 = fmaxf(mx0, v);
        v = (cb     < NKEY) ? sf[t].x[2] + b1a.x : -1e30f; sf[t].x[2] = v; mx1 = fmaxf(mx1, v);
        v = (cb + 1 < NKEY) ? sf[t].x[3] + b1a.y : -1e30f; sf[t].x[3] = v; mx1 = fmaxf(mx1, v);
        v = (cb + 8 < NKEY) ? sf[t].x[6] + b1b.x : -1e30f; sf[t].x[6] = v; mx1 = fmaxf(mx1, v);
        v = (cb + 9 < NKEY) ? sf[t].x[7] + b1b.y : -1e30f; sf[t].x[7] = v; mx1 = fmaxf(mx1, v);
    }
    mx0 = fmaxf(mx0, __shfl_xor_sync(0xffffffffu, mx0, 1));
    mx0 = fmaxf(mx0, __shfl_xor_sync(0xffffffffu, mx0, 2));
    mx1 = fmaxf(mx1, __shfl_xor_sync(0xffffffffu, mx1, 1));
    mx1 = fmaxf(mx1, __shfl_xor_sync(0xffffffffu, mx1, 2));

    float s0 = 0.f, s1 = 0.f;
#pragma unroll
    for (int t = 0; t < 4; ++t) {
        const int cb = t * 16 + c0l;
        float p;
        p = (cb     < NKEY) ? __expf(sf[t].x[0] - mx0) : 0.f; sf[t].x[0] = p; s0 += p;
        p = (cb + 1 < NKEY) ? __expf(sf[t].x[1] - mx0) : 0.f; sf[t].x[1] = p; s0 += p;
        p = (cb + 8 < NKEY) ? __expf(sf[t].x[4] - mx0) : 0.f; sf[t].x[4] = p; s0 += p;
        p = (cb + 9 < NKEY) ? __expf(sf[t].x[5] - mx0) : 0.f; sf[t].x[5] = p; s0 += p;
        p = (cb     < NKEY) ? __expf(sf[t].x[2] - mx1) : 0.f; sf[t].x[2] = p; s1 += p;
        p = (cb + 1 < NKEY) ? __expf(sf[t].x[3] - mx1) : 0.f; sf[t].x[3] = p; s1 += p;
        p = (cb + 8 < NKEY) ? __expf(sf[t].x[6] - mx1) : 0.f; sf[t].x[6] = p; s1 += p;
        p = (cb + 9 < NKEY) ? __expf(sf[t].x[7] - mx1) : 0.f; sf[t].x[7] = p; s1 += p;
    }
    s0 += __shfl_xor_sync(0xffffffffu, s0, 1);
    s0 += __shfl_xor_sync(0xffffffffu, s0, 2);
    s1 += __shfl_xor_sync(0xffffffffu, s1, 1);
    s1 += __shfl_xor_sync(0xffffffffu, s1, 2);
    const float inv0 = 1.0f / s0;
    const float inv1 = 1.0f / s1;

#pragma unroll
    for (int t = 0; t < 4; ++t) {
        pf[t].x[0] = __float2half_rn(sf[t].x[0] * inv0);
        pf[t].x[1] = __float2half_rn(sf[t].x[1] * inv0);
        pf[t].x[4] = __float2half_rn(sf[t].x[4] * inv0);
        pf[t].x[5] = __float2half_rn(sf[t].x[5] * inv0);
        pf[t].x[2] = __float2half_rn(sf[t].x[2] * inv1);
        pf[t].x[3] = __float2half_rn(sf[t].x[3] * inv1);
        pf[t].x[6] = __float2half_rn(sf[t].x[6] * inv1);
        pf[t].x[7] = __float2half_rn(sf[t].x[7] * inv1);
    }
}

// ---- attention for a PAIR of 16-row sub-chunks: shared K/V fragment loads ----
template <bool CLAMP>
__device__ __forceinline__ void attn_pair(const FragA (&qa0)[2], const FragA (&qa1)[2],
                                          const __half* s_k, const __half* s_v,
                                          __half* dst0, __half* dst1, const int* s_qc,
                                          int row0, int h, int lane)
{
    const int base = h * HD_;
    const int r0l = lane >> 2;
    const int c0l = (lane & 3) * 2;

    // S for both sub-chunks; each bk feeds two independent mma chains
    FragC sf0[4], sf1[4];
#pragma unroll
    for (int t = 0; t < 4; ++t) {
        wmma::fill_fragment(sf0[t], 0.0f);
        wmma::fill_fragment(sf1[t], 0.0f);
    }
#pragma unroll
    for (int ks = 0; ks < 2; ++ks) {
#pragma unroll
        for (int t = 0; t < 4; ++t) {
            FragBC bk;
            wmma::load_matrix_sync(bk, s_k + (t * 16) * SKVH + base + ks * 16, SKVH);
            wmma::mma_sync(sf0[t], qa0[ks], bk, sf0[t]);
            wmma::mma_sync(sf1[t], qa1[ks], bk, sf1[t]);
        }
    }

    // softmax both tiles
    FragA pf0[4], pf1[4];
    {
        int i0 = row0 + r0l, i1 = i0 + 8;
        if (CLAMP) { i0 = min(i0, QN_ - 1); i1 = min(i1, QN_ - 1); }
        softmax_pf(sf0, pf0, g_bias_f + (h * 49 + s_qc[i0]) * BSTR,
                   g_bias_f + (h * 49 + s_qc[i1]) * BSTR, c0l);
    }
    {
        int i0 = row0 + 16 + r0l, i1 = i0 + 8;
        if (CLAMP) { i0 = min(i0, QN_ - 1); i1 = min(i1, QN_ - 1); }
        softmax_pf(sf1, pf1, g_bias_f + (h * 49 + s_qc[i0]) * BSTR,
                   g_bias_f + (h * 49 + s_qc[i1]) * BSTR, c0l);
    }

    // PV for both sub-chunks; each bv feeds two independent chains
    FragC o0[2], o1[2];
    wmma::fill_fragment(o0[0], 0.0f);
    wmma::fill_fragment(o0[1], 0.0f);
    wmma::fill_fragment(o1[0], 0.0f);
    wmma::fill_fragment(o1[1], 0.0f);
#pragma unroll
    for (int ks = 0; ks < 4; ++ks) {
#pragma unroll
        for (int t = 0; t < 2; ++t) {
            FragBR bv;
            wmma::load_matrix_sync(bv, s_v + ks * 16 * SKVH + base + t * 16, SKVH);
            wmma::mma_sync(o0[t], pf0[ks], bv, o0[t]);
            wmma::mma_sync(o1[t], pf1[ks], bv, o1[t]);
        }
    }
#pragma unroll
    for (int t = 0; t < 2; ++t) {
        cvt_store_half(dst0 + base + t * 16, SQP, o0[t]);
        cvt_store_half(dst1 + base + t * 16, SQP, o1[t]);
    }
}

// ---- single-sub-chunk attention (tail) ----
__device__ __forceinline__ void attn_single(const FragA (&qa0)[2],
                                            const __half* s_k, const __half* s_v,
                                            __half* dst0, const int* s_qc,
                                            int row0, int h, int lane)
{
    const int base = h * HD_;
    const int r0l = lane >> 2;
    const int c0l = (lane & 3) * 2;

    FragC sf[4];
#pragma unroll
    for (int t = 0; t < 4; ++t) wmma::fill_fragment(sf[t], 0.0f);
#pragma unroll
    for (int ks = 0; ks < 2; ++ks) {
#pragma unroll
        for (int t = 0; t < 4; ++t) {
            FragBC bk;
            wmma::load_matrix_sync(bk, s_k + (t * 16) * SKVH + base + ks * 16, SKVH);
            wmma::mma_sync(sf[t], qa0[ks], bk, sf[t]);
        }
    }

    FragA pf[4];
    {
        int i0 = min(row0 + r0l, QN_ - 1);
        int i1 = min(row0 + r0l + 8, QN_ - 1);
        softmax_pf(sf, pf, g_bias_f + (h * 49 + s_qc[i0]) * BSTR,
                   g_bias_f + (h * 49 + s_qc[i1]) * BSTR, c0l);
    }

    FragC o[2];
    wmma::fill_fragment(o[0], 0.0f);
    wmma::fill_fragment(o[1], 0.0f);
#pragma unroll
    for (int ks = 0; ks < 4; ++ks) {
#pragma unroll
        for (int t = 0; t < 2; ++t) {
            FragBR bv;
            wmma::load_matrix_sync(bv, s_v + ks * 16 * SKVH + base + t * 16, SKVH);
            wmma::mma_sync(o[t], pf[ks], bv, o[t]);
        }
    }
#pragma unroll
    for (int t = 0; t < 2; ++t)
        cvt_store_half(dst0 + base + t * 16, SQP, o[t]);
}

// ---- out projection for MT m-tiles; warp handles n-tile nt ----
template <int MT>
__device__ __forceinline__ void out_proj_block(
    const __half* s_qpb, float* dst, int dst_ld,
    const FragA& ones, int nt, int lane)
{
    FragC c[MT];
#pragma unroll
    for (int m = 0; m < MT; ++m) wmma::fill_fragment(c[m], 0.0f);
    uint4 nb = g_wp_f[nt * 32 + lane];
    for (int ks = 0; ks < 24; ++ks) {
        FragBR bw;
        expand_b(bw, nb);
        nb = g_wp_f[((ks + 1) * 12 + nt) * 32 + lane];
#pragma unroll
        for (int m = 0; m < MT; ++m) {
            FragA a;
            wmma::load_matrix_sync(a, s_qpb + m * 16 * SQP + ks * 16, SQP);
            wmma::mma_sync(c[m], a, bw, c[m]);
        }
    }
    {
        FragBR bw;
        expand_b(bw, nb);
#pragma unroll
        for (int m = 0; m < MT; ++m) wmma::mma_sync(c[m], ones, bw, c[m]);
    }
#pragma unroll
    for (int m = 0; m < MT; ++m)
        wmma::store_matrix_sync(dst + m * 16 * dst_ld + nt * 16, c[m], dst_ld,
                                wmma::mem_row_major);
}

// ---------------- single merged setup kernel ----------------
__global__ void pack_setup(const float* __restrict__ w_kv, const float* __restrict__ b_kv,
                           const float* __restrict__ w_q,  const float* __restrict__ b_q,
                           const float* __restrict__ w_proj, const float* __restrict__ b_proj,
                           const float* __restrict__ bias_table) {
    if (blockIdx.x >= FRAG_BLOCKS) {
        const int idx = (blockIdx.x - FRAG_BLOCKS) * 256 + threadIdx.x;
        if (idx >= BIAS_ELEMS) return;
        const int key = idx & (BSTR - 1);
        const int rem = idx >> 6;            // h*49 + qc
        if (key >= NKEY) { g_bias_f[idx] = 0.0f; return; }
        const int h  = rem / 49;
        const int qc = rem - h * 49;
        const int qi2 = qc / 7, qj2 = qc - qi2 * 7;
        const int kp  = key * 4;
        const int ki  = kp / 14, kj = kp - ki * 14;
        const int dh  = qi2 - (ki >> 1) + 6;
        const int dw  = qj2 - (kj >> 1) + 6;
        g_bias_f[idx] = bias_table[(dh * 13 + dw) * NH_ + h];
        return;
    }
    __shared__ __half tiles[8][256];
    const int w    = blockIdx.x * 8 + (threadIdx.x >> 5);
    const int lane = threadIdx.x & 31;
    __half* tile = tiles[threadIdx.x >> 5];
    uint4* dst;
    if (w < NF_KV) {
        const int ks = w / 48, nt = w - ks * 48, n0 = nt * 16;
        for (int e = lane; e < 256; e += 32) {
            const int r = e >> 4, c = e & 15;
            float v;
            if (ks < 24) v = w_kv[(ks * 16 + r) * 768 + n0 + c];
            else         v = (r == 0) ? b_kv[n0 + c] : 0.0f;
            tile[e] = __float2half_rn(v);
        }
        dst = g_wkv_f + w * 32;
    } else if (w < NF_KV + NF_Q) {
        const int w2 = w - NF_KV, ks = w2 / 24, nt = w2 - ks * 24, n0 = nt * 16;
        for (int e = lane; e < 256; e += 32) {
            const int r = e >> 4, c = e & 15;
            float v;
            if (ks < 12) v = w_q[(ks * 16 + r) * DIM_ + n0 + c] * SCALE_;
            else         v = (r == 0) ? b_q[n0 + c] * SCALE_ : 0.0f;
            tile[e] = __float2half_rn(v);
        }
        dst = g_wq_f + w2 * 32;
    } else if (w < NFRAG) {
        const int w3 = w - NF_KV - NF_Q, ks = w3 / 12, nt = w3 - ks * 12, n0 = nt * 16;
        for (int e = lane; e < 256; e += 32) {
            const int r = e >> 4, c = e & 15;
            float v;
            if (ks < 24) v = w_proj[(ks * 16 + r) * CQ_ + n0 + c];
            else         v = (r == 0) ? b_proj[n0 + c] : 0.0f;
            tile[e] = __float2half_rn(v);
        }
        dst = g_wp_f + w3 * 32;
    } else return;
    __syncwarp();
    FragBR f;
    wmma::load_matrix_sync(f, tile, 16);
    unsigned int w4[4];
#pragma unroll
    for (int i = 0; i < 4; ++i) {
        __half2 h2 = __halves2half2(f.x[2 * i], f.x[2 * i + 1]);
        w4[i] = *reinterpret_cast<unsigned int*>(&h2);
    }
    dst[lane] = make_uint4(w4[0], w4[1], w4[2], w4[3]);
}

// ---------------- main kernel ----------------
__global__ __launch_bounds__(NT, 1)
void wca_kernel(const float* __restrict__ kv, const float* __restrict__ q,
                float* __restrict__ out)
{
    extern __shared__ char smb[];
    __half* s_k   = (__half*)(smb + OFF_K);
    __half* s_v   = (__half*)(smb + OFF_V);
    __half* s_qin = (__half*)(smb + OFF_SCR);
    float*  s_ost = (float*)(smb + OFF_SCR);
    __half* s_qp0 = (__half*)(smb + OFF_QP0);
    __half* s_qp1 = (__half*)(smb + OFF_QP1);
    __half* s_x   = (__half*)(smb + OFF_QP0);
    int*    s_qc  = (int*)(smb + OFF_QC);
    __half* s_one = (__half*)(smb + OFF_ONE);

    const int b    = blockIdx.x;
    const int tid  = threadIdx.x;
    const int wid  = tid >> 5;
    const int lane = tid & 31;

    // ---- phase 0: X load + pad, ones tile, bias cells, chunk-0 q-load ----
    {
        const float4* src = (const float4*)(kv + (size_t)b * NKEY * DIM_);
        for (int i = tid; i < NKEY * 96; i += NT) {
            const int r = i / 96, c4 = (i - r * 96) * 4;
            const float4 v = src[i];
            __half* d = s_x + r * SQP + c4;
            d[0] = __float2half_rn(v.x); d[1] = __float2half_rn(v.y);
            d[2] = __float2half_rn(v.z); d[3] = __float2half_rn(v.w);
        }
        for (int i = tid; i < (NKP - NKEY) * SQP; i += NT)
            s_x[NKEY * SQP + i] = __float2half_rn(0.0f);
        if (tid < 256) s_one[tid] = __float2half_rn((tid & 15) == 0 ? 1.0f : 0.0f);
        if (tid < QN_) {
            const int qi = tid / 14, qj = tid - qi * 14;
            s_qc[tid] = (qi >> 1) * 7 + (qj >> 1);
        }
        const float4* qsrc = (const float4*)(q + (size_t)b * QN_ * CQ_);
        for (int i = tid; i < CHUNK * 48; i += NT) {
            const int r = i / 48, c4 = (i - r * 48) * 4;
            const float4 v = qsrc[i];
            __half* d = s_qin + r * SQIN + c4;
            d[0] = __float2half_rn(v.x); d[1] = __float2half_rn(v.y);
            d[2] = __float2half_rn(v.z); d[3] = __float2half_rn(v.w);
        }
    }
    __syncthreads();

    FragA ones;
    wmma::load_matrix_sync(ones, s_one, 16);

    // ---- phase 1: kv projection, B-stationary over 4 m-tiles ----
    {
        for (int j = 0; j < 2; ++j) {
            const int nt0 = (wid * 2 + j) * 2;
            FragC c[4][2];
#pragma unroll
            for (int m = 0; m < 4; ++m) {
                wmma::fill_fragment(c[m][0], 0.0f);
                wmma::fill_fragment(c[m][1], 0.0f);
            }
            uint4 nb0 = g_wkv_f[nt0 * 32 + lane];
            uint4 nb1 = g_wkv_f[(nt0 + 1) * 32 + lane];
            for (int ks = 0; ks < 24; ++ks) {
                FragBR b0, b1;
                expand_b(b0, nb0);
                expand_b(b1, nb1);
                nb0 = g_wkv_f[((ks + 1) * 48 + nt0) * 32 + lane];
                nb1 = g_wkv_f[((ks + 1) * 48 + nt0 + 1) * 32 + lane];
#pragma unroll
                for (int m = 0; m < 4; ++m) {
                    FragA a;
                    wmma::load_matrix_sync(a, s_x + m * 16 * SQP + ks * 16, SQP);
                    wmma::mma_sync(c[m][0], a, b0, c[m][0]);
                    wmma::mma_sync(c[m][1], a, b1, c[m][1]);
                }
            }
            {
                FragBR b0, b1;
                expand_b(b0, nb0);
                expand_b(b1, nb1);
#pragma unroll
                for (int m = 0; m < 4; ++m) {
                    wmma::mma_sync(c[m][0], ones, b0, c[m][0]);
                    wmma::mma_sync(c[m][1], ones, b1, c[m][1]);
                }
            }
#pragma unroll
            for (int t = 0; t < 2; ++t) {
                const int colg = (nt0 + t) * 16;
                __half* dst = (colg < DIM_) ? (s_k + colg) : (s_v + colg - DIM_);
#pragma unroll
                for (int m = 0; m < 4; ++m)
                    cvt_store_half(dst + m * 16 * SKVH, SKVH, c[m][t]);
            }
        }
    }
    __syncthreads();   // K/V ready; qin(0) ready

    const size_t ob_base = (size_t)b * QN_ * CQ_;

    // ---- phase 2: 3 full chunks, pipelined out-proj ----
    for (int i = 0; i < 3; ++i) {
        const int q0 = i * CHUNK;
        __half* qpw = (i & 1) ? s_qp1 : s_qp0;

        FragA qa[4][2];
        qproj<4>(s_qin, qa, ones, wid, lane);

        if (i > 0) {
            const __half* qpr = ((i - 1) & 1) ? s_qp1 : s_qp0;
            out_proj_block<4>(qpr, out + ob_base + (size_t)(q0 - CHUNK) * CQ_,
                              CQ_, ones, wid, lane);
        }

        attn_pair<false>(qa[0], qa[1], s_k, s_v, qpw, qpw + 16 * SQP,
                         s_qc, q0, wid, lane);
        attn_pair<false>(qa[2], qa[3], s_k, s_v, qpw + 32 * SQP, qpw + 48 * SQP,
                         s_qc, q0 + 32, wid, lane);
        __syncthreads();   // O(i) complete; qin consumed

        // load next chunk's q rows
        {
            const int q0n = q0 + CHUNK;
            const int nrn = (i == 2) ? (QN_ - 3 * CHUNK) : CHUNK;   // 4 or 64
            const int mtn = (i == 2) ? 1 : 4;
            const float4* src = (const float4*)(q + ob_base + (size_t)q0n * CQ_);
            for (int e = tid; e < mtn * 16 * 48; e += NT) {
                const int r = e / 48, c4 = (e - r * 48) * 4;
                float4 v = make_float4(0.f, 0.f, 0.f, 0.f);
                if (r < nrn) v = src[e];
                __half* d = s_qin + r * SQIN + c4;
                d[0] = __float2half_rn(v.x); d[1] = __float2half_rn(v.y);
                d[2] = __float2half_rn(v.z); d[3] = __float2half_rn(v.w);
            }
            __syncthreads();
        }
    }

    // ---- tail chunk (rows 192..195, MT=1) ----
    {
        FragA qa1[1][2];
        qproj<1>(s_qin, qa1, ones, wid, lane);

        out_proj_block<4>(s_qp0, out + ob_base + (size_t)(2 * CHUNK) * CQ_,
                          CQ_, ones, wid, lane);

        attn_single(qa1[0], s_k, s_v, s_qp1, s_qc, 3 * CHUNK, wid, lane);
        __syncthreads();

        out_proj_block<1>(s_qp1, s_ost, CQ_, ones, wid, lane);
        __syncthreads();

        const int nrl = QN_ - 3 * CHUNK;   // 4
        float4* ob = (float4*)(out + ob_base + (size_t)(3 * CHUNK) * CQ_);
        for (int e = tid; e < nrl * 48; e += NT) ob[e] = ((float4*)s_ost)[e];
    }
}

extern "C" void kernel_launch(void* const* d_in, const int* in_sizes, int n_in,
                              void* d_out, int out_size) {
    const float* kv         = (const float*)d_in[0];
    const float* q          = (const float*)d_in[1];
    const float* w_kv       = (const float*)d_in[2];
    const float* b_kv       = (const float*)d_in[3];
    const float* w_q        = (const float*)d_in[4];
    const float* b_q        = (const float*)d_in[5];
    const float* bias_table = (const float*)d_in[6];
    const float* w_proj     = (const float*)d_in[7];
    const float* b_proj     = (const float*)d_in[8];
    float* out = (float*)d_out;

    const int B = in_sizes[0] / (NKEY * DIM_);              // 2048
    pack_setup<<<FRAG_BLOCKS + BIAS_BLOCKS, 256>>>(w_kv, b_kv, w_q, b_q,
                                                   w_proj, b_proj, bias_table);

    cudaFuncSetAttribute(wca_kernel, cudaFuncAttributeMaxDynamicSharedMemorySize, SMEM_BYTES);
    wca_kernel<<<B, NT, SMEM_BYTES>>>(kv, q, out);
}

// round 15
// speedup vs baseline: 1.3654x; 1.0006x over previous
#include <cuda_runtime.h>
#include <cuda_fp16.h>
#include <mma.h>
#include <cstdint>

using namespace nvcuda;

namespace {
constexpr int NKEY = 49;
constexpr int QN_  = 196;
constexpr int DIM_ = 384;
constexpr int NH_  = 12;
constexpr int HD_  = 32;
constexpr int CQ_  = 192;
constexpr float SCALE_ = 0.17677669529663687f;

constexpr int NT    = 384;   // 12 warps
constexpr int NW    = 12;
constexpr int CHUNK = 64;
constexpr int NKP   = 64;

constexpr int SKVH = 392;    // K/V row stride (halves)
constexpr int SQP  = 392;    // qp / x row stride (halves)
constexpr int SQIN = 200;    // q-input row stride (halves)
constexpr int BSTR = 64;     // bias row stride (floats)

// smem byte offsets
constexpr int OFF_K   = 0;                // 64*392*2 = 50176
constexpr int OFF_V   = 50176;
constexpr int OFF_SCR = 100352;           // qin 64x200 half / ost 16x192 f32
constexpr int OFF_QP0 = 125952;           // 64x392 half (phase1: s_x overlays)
constexpr int OFF_QP1 = 176128;           // 64x392 half
constexpr int OFF_QC  = 226304;           // 196 ints
constexpr int OFF_ONE = 227088;
constexpr int SMEM_BYTES = 227600;

using FragA  = wmma::fragment<wmma::matrix_a, 16, 16, 16, __half, wmma::row_major>;
using FragBR = wmma::fragment<wmma::matrix_b, 16, 16, 16, __half, wmma::row_major>;
using FragBC = wmma::fragment<wmma::matrix_b, 16, 16, 16, __half, wmma::col_major>;
using FragC  = wmma::fragment<wmma::accumulator, 16, 16, 16, float>;
using FragCH = wmma::fragment<wmma::accumulator, 16, 16, 16, __half>;

constexpr int NF_KV = 25 * 48;
constexpr int NF_Q  = 13 * 24;
constexpr int NF_P  = 25 * 12;
constexpr int NFRAG = NF_KV + NF_Q + NF_P;        // 1812
constexpr int FRAG_BLOCKS = (NFRAG + 7) / 8;      // 227
constexpr int BIAS_ELEMS  = NH_ * 49 * BSTR;      // 37632
constexpr int BIAS_BLOCKS = (BIAS_ELEMS + 255) / 256;
}

__device__ uint4 g_wkv_f[NF_KV * 32];
__device__ uint4 g_wq_f [NF_Q  * 32];
__device__ uint4 g_wp_f [NF_P  * 32];
__device__ float g_bias_f[BIAS_ELEMS];

__device__ __forceinline__ void expand_b(FragBR& f, uint4 v) {
    unsigned int w[4] = {v.x, v.y, v.z, v.w};
#pragma unroll
    for (int i = 0; i < 4; ++i) {
        const __half2 h2 = *reinterpret_cast<const __half2*>(&w[i]);
        f.x[2 * i]     = __low2half(h2);
        f.x[2 * i + 1] = __high2half(h2);
    }
}

__device__ __forceinline__ void cvt_store_half(__half* dst, int ld, const FragC& c) {
    FragCH h;
#pragma unroll
    for (int i = 0; i < 8; ++i) h.x[i] = __float2half_rn(c.x[i]);
    wmma::store_matrix_sync(dst, h, ld, wmma::mem_row_major);
}

__device__ __forceinline__ void cvt_acc_to_a(FragA& a, const FragC& c) {
#pragma unroll
    for (int i = 0; i < 8; ++i) a.x[i] = __float2half_rn(c.x[i]);
}

// ---- q projection for MT m-tiles of head h; results as register A-fragments ----
template <int MT>
__device__ __forceinline__ void qproj(const __half* s_qin, FragA (&qa)[MT][2],
                                      const FragA& ones, int h, int lane)
{
    const int nt0 = h * 2;
    FragC qc[MT][2];
#pragma unroll
    for (int m = 0; m < MT; ++m) {
        wmma::fill_fragment(qc[m][0], 0.0f);
        wmma::fill_fragment(qc[m][1], 0.0f);
    }
    uint4 nb0 = g_wq_f[nt0 * 32 + lane];
    uint4 nb1 = g_wq_f[(nt0 + 1) * 32 + lane];
    for (int ks = 0; ks < 12; ++ks) {
        FragBR b0, b1;
        expand_b(b0, nb0);
        expand_b(b1, nb1);
        nb0 = g_wq_f[((ks + 1) * 24 + nt0) * 32 + lane];
        nb1 = g_wq_f[((ks + 1) * 24 + nt0 + 1) * 32 + lane];
#pragma unroll
        for (int m = 0; m < MT; ++m) {
            FragA a;
            wmma::load_matrix_sync(a, s_qin + m * 16 * SQIN + ks * 16, SQIN);
            wmma::mma_sync(qc[m][0], a, b0, qc[m][0]);
            wmma::mma_sync(qc[m][1], a, b1, qc[m][1]);
        }
    }
    {
        FragBR b0, b1;
        expand_b(b0, nb0);
        expand_b(b1, nb1);
#pragma unroll
        for (int m = 0; m < MT; ++m) {
            wmma::mma_sync(qc[m][0], ones, b0, qc[m][0]);
            wmma::mma_sync(qc[m][1], ones, b1, qc[m][1]);
        }
    }
#pragma unroll
    for (int m = 0; m < MT; ++m) {
        cvt_acc_to_a(qa[m][0], qc[m][0]);
        cvt_acc_to_a(qa[m][1], qc[m][1]);
    }
}

// ---- softmax on one 16x64 S tile (registers) -> pre-normalized half P ----
__device__ __forceinline__ void softmax_pf(FragC (&sf)[4], FragA (&pf)[4],
                                           const float* bias0, const float* bias1,
                                           int c0l)
{
    float mx0 = -1e30f, mx1 = -1e30f;
#pragma unroll
    for (int t = 0; t < 4; ++t) {
        const int cb = t * 16 + c0l;
        const float2 b0a = *(const float2*)(bias0 + cb);
        const float2 b0b = *(const float2*)(bias0 + cb + 8);
        const float2 b1a = *(const float2*)(bias1 + cb);
        const float2 b1b = *(const float2*)(bias1 + cb + 8);
        float v;
        v = (cb     < NKEY) ? sf[t].x[0] + b0a.x : -1e30f; sf[t].x[0] = v; mx0 = fmaxf(mx0, v);
        v = (cb + 1 < NKEY) ? sf[t].x[1] + b0a.y : -1e30f; sf[t].x[1] = v; mx0 = fmaxf(mx0, v);
        v = (cb + 8 < NKEY) ? sf[t].x[4] + b0b.x : -1e30f; sf[t].x[4] = v; mx0 = fmaxf(mx0, v);
        v = (cb + 9 < NKEY) ? sf[t].x[5] + b0b.y : -1e30f; sf[t].x[5] = v; mx0 = fmaxf(mx0, v);
        v = (cb     < NKEY) ? sf[t].x[2] + b1a.x : -1e30f; sf[t].x[2] = v; mx1 = fmaxf(mx1, v);
        v = (cb + 1 < NKEY) ? sf[t].x[3] + b1a.y : -1e30f; sf[t].x[3] = v; mx1 = fmaxf(mx1, v);
        v = (cb + 8 < NKEY) ? sf[t].x[6] + b1b.x : -1e30f; sf[t].x[6] = v; mx1 = fmaxf(mx1, v);
        v = (cb + 9 < NKEY) ? sf[t].x[7] + b1b.y : -1e30f; sf[t].x[7] = v; mx1 = fmaxf(mx1, v);
    }
    mx0 = fmaxf(mx0, __shfl_xor_sync(0xffffffffu, mx0, 1));
    mx0 = fmaxf(mx0, __shfl_xor_sync(0xffffffffu, mx0, 2));
    mx1 = fmaxf(mx1, __shfl_xor_sync(0xffffffffu, mx1, 1));
    mx1 = fmaxf(mx1, __shfl_xor_sync(0xffffffffu, mx1, 2));

    float s0 = 0.f, s1 = 0.f;
#pragma unroll
    for (int t = 0; t < 4; ++t) {
        const int cb = t * 16 + c0l;
        float p;
        p = (cb     < NKEY) ? __expf(sf[t].x[0] - mx0) : 0.f; sf[t].x[0] = p; s0 += p;
        p = (cb + 1 < NKEY) ? __expf(sf[t].x[1] - mx0) : 0.f; sf[t].x[1] = p; s0 += p;
        p = (cb + 8 < NKEY) ? __expf(sf[t].x[4] - mx0) : 0.f; sf[t].x[4] = p; s0 += p;
        p = (cb + 9 < NKEY) ? __expf(sf[t].x[5] - mx0) : 0.f; sf[t].x[5] = p; s0 += p;
        p = (cb     < NKEY) ? __expf(sf[t].x[2] - mx1) : 0.f; sf[t].x[2] = p; s1 += p;
        p = (cb + 1 < NKEY) ? __expf(sf[t].x[3] - mx1) : 0.f; sf[t].x[3] = p; s1 += p;
        p = (cb + 8 < NKEY) ? __expf(sf[t].x[6] - mx1) : 0.f; sf[t].x[6] = p; s1 += p;
        p = (cb + 9 < NKEY) ? __expf(sf[t].x[7] - mx1) : 0.f; sf[t].x[7] = p; s1 += p;
    }
    s0 += __shfl_xor_sync(0xffffffffu, s0, 1);
    s0 += __shfl_xor_sync(0xffffffffu, s0, 2);
    s1 += __shfl_xor_sync(0xffffffffu, s1, 1);
    s1 += __shfl_xor_sync(0xffffffffu, s1, 2);
    const float inv0 = 1.0f / s0;
    const float inv1 = 1.0f / s1;

#pragma unroll
    for (int t = 0; t < 4; ++t) {
        pf[t].x[0] = __float2half_rn(sf[t].x[0] * inv0);
        pf[t].x[1] = __float2half_rn(sf[t].x[1] * inv0);
        pf[t].x[4] = __float2half_rn(sf[t].x[4] * inv0);
        pf[t].x[5] = __float2half_rn(sf[t].x[5] * inv0);
        pf[t].x[2] = __float2half_rn(sf[t].x[2] * inv1);
        pf[t].x[3] = __float2half_rn(sf[t].x[3] * inv1);
        pf[t].x[6] = __float2half_rn(sf[t].x[6] * inv1);
        pf[t].x[7] = __float2half_rn(sf[t].x[7] * inv1);
    }
}

// ---- attention for a PAIR of 16-row sub-chunks: shared K/V fragment loads ----
template <bool CLAMP>
__device__ __forceinline__ void attn_pair(const FragA (&qa0)[2], const FragA (&qa1)[2],
                                          const __half* s_k, const __half* s_v,
                                          __half* dst0, __half* dst1, const int* s_qc,
                                          int row0, int h, int lane)
{
    const int base = h * HD_;
    const int r0l = lane >> 2;
    const int c0l = (lane & 3) * 2;

    // S for both sub-chunks; each bk feeds two independent mma chains
    FragC sf0[4], sf1[4];
#pragma unroll
    for (int t = 0; t < 4; ++t) {
        wmma::fill_fragment(sf0[t], 0.0f);
        wmma::fill_fragment(sf1[t], 0.0f);
    }
#pragma unroll
    for (int ks = 0; ks < 2; ++ks) {
#pragma unroll
        for (int t = 0; t < 4; ++t) {
            FragBC bk;
            wmma::load_matrix_sync(bk, s_k + (t * 16) * SKVH + base + ks * 16, SKVH);
            wmma::mma_sync(sf0[t], qa0[ks], bk, sf0[t]);
            wmma::mma_sync(sf1[t], qa1[ks], bk, sf1[t]);
        }
    }

    // softmax both tiles
    FragA pf0[4], pf1[4];
    {
        int i0 = row0 + r0l, i1 = i0 + 8;
        if (CLAMP) { i0 = min(i0, QN_ - 1); i1 = min(i1, QN_ - 1); }
        softmax_pf(sf0, pf0, g_bias_f + (h * 49 + s_qc[i0]) * BSTR,
                   g_bias_f + (h * 49 + s_qc[i1]) * BSTR, c0l);
    }
    {
        int i0 = row0 + 16 + r0l, i1 = i0 + 8;
        if (CLAMP) { i0 = min(i0, QN_ - 1); i1 = min(i1, QN_ - 1); }
        softmax_pf(sf1, pf1, g_bias_f + (h * 49 + s_qc[i0]) * BSTR,
                   g_bias_f + (h * 49 + s_qc[i1]) * BSTR, c0l);
    }

    // PV for both sub-chunks; each bv feeds two independent chains
    FragC o0[2], o1[2];
    wmma::fill_fragment(o0[0], 0.0f);
    wmma::fill_fragment(o0[1], 0.0f);
    wmma::fill_fragment(o1[0], 0.0f);
    wmma::fill_fragment(o1[1], 0.0f);
#pragma unroll
    for (int ks = 0; ks < 4; ++ks) {
#pragma unroll
        for (int t = 0; t < 2; ++t) {
            FragBR bv;
            wmma::load_matrix_sync(bv, s_v + ks * 16 * SKVH + base + t * 16, SKVH);
            wmma::mma_sync(o0[t], pf0[ks], bv, o0[t]);
            wmma::mma_sync(o1[t], pf1[ks], bv, o1[t]);
        }
    }
#pragma unroll
    for (int t = 0; t < 2; ++t) {
        cvt_store_half(dst0 + base + t * 16, SQP, o0[t]);
        cvt_store_half(dst1 + base + t * 16, SQP, o1[t]);
    }
}

// ---- single-sub-chunk attention (tail) ----
__device__ __forceinline__ void attn_single(const FragA (&qa0)[2],
                                            const __half* s_k, const __half* s_v,
                                            __half* dst0, const int* s_qc,
                                            int row0, int h, int lane)
{
    const int base = h * HD_;
    const int r0l = lane >> 2;
    const int c0l = (lane & 3) * 2;

    FragC sf[4];
#pragma unroll
    for (int t = 0; t < 4; ++t) wmma::fill_fragment(sf[t], 0.0f);
#pragma unroll
    for (int ks = 0; ks < 2; ++ks) {
#pragma unroll
        for (int t = 0; t < 4; ++t) {
            FragBC bk;
            wmma::load_matrix_sync(bk, s_k + (t * 16) * SKVH + base + ks * 16, SKVH);
            wmma::mma_sync(sf[t], qa0[ks], bk, sf[t]);
        }
    }

    FragA pf[4];
    {
        int i0 = min(row0 + r0l, QN_ - 1);
        int i1 = min(row0 + r0l + 8, QN_ - 1);
        softmax_pf(sf, pf, g_bias_f + (h * 49 + s_qc[i0]) * BSTR,
                   g_bias_f + (h * 49 + s_qc[i1]) * BSTR, c0l);
    }

    FragC o[2];
    wmma::fill_fragment(o[0], 0.0f);
    wmma::fill_fragment(o[1], 0.0f);
#pragma unroll
    for (int ks = 0; ks < 4; ++ks) {
#pragma unroll
        for (int t = 0; t < 2; ++t) {
            FragBR bv;
            wmma::load_matrix_sync(bv, s_v + ks * 16 * SKVH + base + t * 16, SKVH);
            wmma::mma_sync(o[t], pf[ks], bv, o[t]);
        }
    }
#pragma unroll
    for (int t = 0; t < 2; ++t)
        cvt_store_half(dst0 + base + t * 16, SQP, o[t]);
}

// ---- out projection for MT m-tiles; warp handles n-tile nt ----
template <int MT>
__device__ __forceinline__ void out_proj_block(
    const __half* s_qpb, float* dst, int dst_ld,
    const FragA& ones, int nt, int lane)
{
    FragC c[MT];
#pragma unroll
    for (int m = 0; m < MT; ++m) wmma::fill_fragment(c[m], 0.0f);
    uint4 nb = g_wp_f[nt * 32 + lane];
    for (int ks = 0; ks < 24; ++ks) {
        FragBR bw;
        expand_b(bw, nb);
        nb = g_wp_f[((ks + 1) * 12 + nt) * 32 + lane];
#pragma unroll
        for (int m = 0; m < MT; ++m) {
            FragA a;
            wmma::load_matrix_sync(a, s_qpb + m * 16 * SQP + ks * 16, SQP);
            wmma::mma_sync(c[m], a, bw, c[m]);
        }
    }
    {
        FragBR bw;
        expand_b(bw, nb);
#pragma unroll
        for (int m = 0; m < MT; ++m) wmma::mma_sync(c[m], ones, bw, c[m]);
    }
#pragma unroll
    for (int m = 0; m < MT; ++m)
        wmma::store_matrix_sync(dst + m * 16 * dst_ld + nt * 16, c[m], dst_ld,
                                wmma::mem_row_major);
}

// ---------------- single merged setup kernel ----------------
__global__ void pack_setup(const float* __restrict__ w_kv, const float* __restrict__ b_kv,
                           const float* __restrict__ w_q,  const float* __restrict__ b_q,
                           const float* __restrict__ w_proj, const float* __restrict__ b_proj,
                           const float* __restrict__ bias_table) {
    if (blockIdx.x >= FRAG_BLOCKS) {
        const int idx = (blockIdx.x - FRAG_BLOCKS) * 256 + threadIdx.x;
        if (idx >= BIAS_ELEMS) return;
        const int key = idx & (BSTR - 1);
        const int rem = idx >> 6;            // h*49 + qc
        if (key >= NKEY) { g_bias_f[idx] = 0.0f; return; }
        const int h  = rem / 49;
        const int qc = rem - h * 49;
        const int qi2 = qc / 7, qj2 = qc - qi2 * 7;
        const int kp  = key * 4;
        const int ki  = kp / 14, kj = kp - ki * 14;
        const int dh  = qi2 - (ki >> 1) + 6;
        const int dw  = qj2 - (kj >> 1) + 6;
        g_bias_f[idx] = bias_table[(dh * 13 + dw) * NH_ + h];
        return;
    }
    __shared__ __half tiles[8][256];
    const int w    = blockIdx.x * 8 + (threadIdx.x >> 5);
    const int lane = threadIdx.x & 31;
    __half* tile = tiles[threadIdx.x >> 5];
    uint4* dst;
    if (w < NF_KV) {
        const int ks = w / 48, nt = w - ks * 48, n0 = nt * 16;
        for (int e = lane; e < 256; e += 32) {
            const int r = e >> 4, c = e & 15;
            float v;
            if (ks < 24) v = w_kv[(ks * 16 + r) * 768 + n0 + c];
            else         v = (r == 0) ? b_kv[n0 + c] : 0.0f;
            tile[e] = __float2half_rn(v);
        }
        dst = g_wkv_f + w * 32;
    } else if (w < NF_KV + NF_Q) {
        const int w2 = w - NF_KV, ks = w2 / 24, nt = w2 - ks * 24, n0 = nt * 16;
        for (int e = lane; e < 256; e += 32) {
            const int r = e >> 4, c = e & 15;
            float v;
            if (ks < 12) v = w_q[(ks * 16 + r) * DIM_ + n0 + c] * SCALE_;
            else         v = (r == 0) ? b_q[n0 + c] * SCALE_ : 0.0f;
            tile[e] = __float2half_rn(v);
        }
        dst = g_wq_f + w2 * 32;
    } else if (w < NFRAG) {
        const int w3 = w - NF_KV - NF_Q, ks = w3 / 12, nt = w3 - ks * 12, n0 = nt * 16;
        for (int e = lane; e < 256; e += 32) {
            const int r = e >> 4, c = e & 15;
            float v;
            if (ks < 24) v = w_proj[(ks * 16 + r) * CQ_ + n0 + c];
            else         v = (r == 0) ? b_proj[n0 + c] : 0.0f;
            tile[e] = __float2half_rn(v);
        }
        dst = g_wp_f + w3 * 32;
    } else return;
    __syncwarp();
    FragBR f;
    wmma::load_matrix_sync(f, tile, 16);
    unsigned int w4[4];
#pragma unroll
    for (int i = 0; i < 4; ++i) {
        __half2 h2 = __halves2half2(f.x[2 * i], f.x[2 * i + 1]);
        w4[i] = *reinterpret_cast<unsigned int*>(&h2);
    }
    dst[lane] = make_uint4(w4[0], w4[1], w4[2], w4[3]);
}

// ---------------- main kernel ----------------
__global__ __launch_bounds__(NT, 1)
void wca_kernel(const float* __restrict__ kv, const float* __restrict__ q,
                float* __restrict__ out)
{
    extern __shared__ char smb[];
    __half* s_k   = (__half*)(smb + OFF_K);
    __half* s_v   = (__half*)(smb + OFF_V);
    __half* s_qin = (__half*)(smb + OFF_SCR);
    float*  s_ost = (float*)(smb + OFF_SCR);
    __half* s_qp0 = (__half*)(smb + OFF_QP0);
    __half* s_qp1 = (__half*)(smb + OFF_QP1);
    __half* s_x   = (__half*)(smb + OFF_QP0);
    int*    s_qc  = (int*)(smb + OFF_QC);
    __half* s_one = (__half*)(smb + OFF_ONE);

    const int b    = blockIdx.x;
    const int tid  = threadIdx.x;
    const int wid  = tid >> 5;
    const int lane = tid & 31;

    // ---- phase 0: X load + pad, ones tile, bias cells, chunk-0 q-load ----
    {
        const float4* src = (const float4*)(kv + (size_t)b * NKEY * DIM_);
        for (int i = tid; i < NKEY * 96; i += NT) {
            const int r = i / 96, c4 = (i - r * 96) * 4;
            const float4 v = src[i];
            __half* d = s_x + r * SQP + c4;
            d[0] = __float2half_rn(v.x); d[1] = __float2half_rn(v.y);
            d[2] = __float2half_rn(v.z); d[3] = __float2half_rn(v.w);
        }
        for (int i = tid; i < (NKP - NKEY) * SQP; i += NT)
            s_x[NKEY * SQP + i] = __float2half_rn(0.0f);
        if (tid < 256) s_one[tid] = __float2half_rn((tid & 15) == 0 ? 1.0f : 0.0f);
        if (tid < QN_) {
            const int qi = tid / 14, qj = tid - qi * 14;
            s_qc[tid] = (qi >> 1) * 7 + (qj >> 1);
        }
        const float4* qsrc = (const float4*)(q + (size_t)b * QN_ * CQ_);
        for (int i = tid; i < CHUNK * 48; i += NT) {
            const int r = i / 48, c4 = (i - r * 48) * 4;
            const float4 v = qsrc[i];
            __half* d = s_qin + r * SQIN + c4;
            d[0] = __float2half_rn(v.x); d[1] = __float2half_rn(v.y);
            d[2] = __float2half_rn(v.z); d[3] = __float2half_rn(v.w);
        }
    }
    __syncthreads();

    FragA ones;
    wmma::load_matrix_sync(ones, s_one, 16);

    // ---- phase 1: kv projection, B-stationary over 4 m-tiles ----
    {
        for (int j = 0; j < 2; ++j) {
            const int nt0 = (wid * 2 + j) * 2;
            FragC c[4][2];
#pragma unroll
            for (int m = 0; m < 4; ++m) {
                wmma::fill_fragment(c[m][0], 0.0f);
                wmma::fill_fragment(c[m][1], 0.0f);
            }
            uint4 nb0 = g_wkv_f[nt0 * 32 + lane];
            uint4 nb1 = g_wkv_f[(nt0 + 1) * 32 + lane];
            for (int ks = 0; ks < 24; ++ks) {
                FragBR b0, b1;
                expand_b(b0, nb0);
                expand_b(b1, nb1);
                nb0 = g_wkv_f[((ks + 1) * 48 + nt0) * 32 + lane];
                nb1 = g_wkv_f[((ks + 1) * 48 + nt0 + 1) * 32 + lane];
#pragma unroll
                for (int m = 0; m < 4; ++m) {
                    FragA a;
                    wmma::load_matrix_sync(a, s_x + m * 16 * SQP + ks * 16, SQP);
                    wmma::mma_sync(c[m][0], a, b0, c[m][0]);
                    wmma::mma_sync(c[m][1], a, b1, c[m][1]);
                }
            }
            {
                FragBR b0, b1;
                expand_b(b0, nb0);
                expand_b(b1, nb1);
#pragma unroll
                for (int m = 0; m < 4; ++m) {
                    wmma::mma_sync(c[m][0], ones, b0, c[m][0]);
                    wmma::mma_sync(c[m][1], ones, b1, c[m][1]);
                }
            }
#pragma unroll
            for (int t = 0; t < 2; ++t) {
                const int colg = (nt0 + t) * 16;
                __half* dst = (colg < DIM_) ? (s_k + colg) : (s_v + colg - DIM_);
#pragma unroll
                for (int m = 0; m < 4; ++m)
                    cvt_store_half(dst + m * 16 * SKVH, SKVH, c[m][t]);
            }
        }
    }
    __syncthreads();   // K/V ready; qin(0) ready

    const size_t ob_base = (size_t)b * QN_ * CQ_;

    // ---- phase 2: 3 full chunks, pipelined out-proj ----
    for (int i = 0; i < 3; ++i) {
        const int q0 = i * CHUNK;
        __half* qpw = (i & 1) ? s_qp1 : s_qp0;

        FragA qa[4][2];
        qproj<4>(s_qin, qa, ones, wid, lane);

        if (i > 0) {
            const __half* qpr = ((i - 1) & 1) ? s_qp1 : s_qp0;
            out_proj_block<4>(qpr, out + ob_base + (size_t)(q0 - CHUNK) * CQ_,
                              CQ_, ones, wid, lane);
        }

        attn_pair<false>(qa[0], qa[1], s_k, s_v, qpw, qpw + 16 * SQP,
                         s_qc, q0, wid, lane);
        attn_pair<false>(qa[2], qa[3], s_k, s_v, qpw + 32 * SQP, qpw + 48 * SQP,
                         s_qc, q0 + 32, wid, lane);
        __syncthreads();   // O(i) complete; qin consumed

        // load next chunk's q rows
        {
            const int q0n = q0 + CHUNK;
            const int nrn = (i == 2) ? (QN_ - 3 * CHUNK) : CHUNK;   // 4 or 64
            const int mtn = (i == 2) ? 1 : 4;
            const float4* src = (const float4*)(q + ob_base + (size_t)q0n * CQ_);
            for (int e = tid; e < mtn * 16 * 48; e += NT) {
                const int r = e / 48, c4 = (e - r * 48) * 4;
                float4 v = make_float4(0.f, 0.f, 0.f, 0.f);
                if (r < nrn) v = src[e];
                __half* d = s_qin + r * SQIN + c4;
                d[0] = __float2half_rn(v.x); d[1] = __float2half_rn(v.y);
                d[2] = __float2half_rn(v.z); d[3] = __float2half_rn(v.w);
            }
            __syncthreads();
        }
    }

    // ---- tail chunk (rows 192..195, MT=1) ----
    {
        FragA qa1[1][2];
        qproj<1>(s_qin, qa1, ones, wid, lane);

        out_proj_block<4>(s_qp0, out + ob_base + (size_t)(2 * CHUNK) * CQ_,
                          CQ_, ones, wid, lane);

        attn_single(qa1[0], s_k, s_v, s_qp1, s_qc, 3 * CHUNK, wid, lane);
        __syncthreads();

        out_proj_block<1>(s_qp1, s_ost, CQ_, ones, wid, lane);
        __syncthreads();

        const int nrl = QN_ - 3 * CHUNK;   // 4
        float4* ob = (float4*)(out + ob_base + (size_t)(3 * CHUNK) * CQ_);
        for (int e = tid; e < nrl * 48; e += NT) ob[e] = ((float4*)s_ost)[e];
    }
}

extern "C" void kernel_launch(void* const* d_in, const int* in_sizes, int n_in,
                              void* d_out, int out_size) {
    const float* kv         = (const float*)d_in[0];
    const float* q          = (const float*)d_in[1];
    const float* w_kv       = (const float*)d_in[2];
    const float* b_kv       = (const float*)d_in[3];
    const float* w_q        = (const float*)d_in[4];
    const float* b_q        = (const float*)d_in[5];
    const float* bias_table = (const float*)d_in[6];
    const float* w_proj     = (const float*)d_in[7];
    const float* b_proj     = (const float*)d_in[8];
    float* out = (float*)d_out;

    const int B = in_sizes[0] / (NKEY * DIM_);              // 2048
    pack_setup<<<FRAG_BLOCKS + BIAS_BLOCKS, 256>>>(w_kv, b_kv, w_q, b_q,
                                                   w_proj, b_proj, bias_table);

    cudaFuncSetAttribute(wca_kernel, cudaFuncAttributeMaxDynamicSharedMemorySize, SMEM_BYTES);
    wca_kernel<<<B, NT, SMEM_BYTES>>>(kv, q, out);
}